// round 10
// baseline (speedup 1.0000x reference)
#include <cuda_runtime.h>
#include <cuda_bf16.h>
#include <cstdint>

#define BB 2
#define SS 2048
#define DD 1024
#define HH 16
#define HDD 64
#define MROWS (BB*SS)    // 4096
#define NCOLS (HH*HDD)   // 1024

// ---------------- scratch (__device__ globals; allocation-free rule) ----------------
__device__ float g_q  [(size_t)MROWS*NCOLS];  // [B,H,S,HD], tf32-rounded, pre-scaled 1/8
__device__ float g_k  [(size_t)MROWS*NCOLS];  // [B,H,S,HD], tf32-rounded
__device__ __nv_bfloat16 g_vhi[(size_t)MROWS*NCOLS]; // V^T [B,H,HD,S] bf16 hi
__device__ __nv_bfloat16 g_vlo[(size_t)MROWS*NCOLS]; // V^T bf16 lo
__device__ float g_o  [(size_t)MROWS*NCOLS];  // [B,S,H*HD] attention out
__device__ __nv_bfloat16 g_xhi[(size_t)MROWS*DD];    // x split, bf16
__device__ __nv_bfloat16 g_xlo[(size_t)MROWS*DD];
__device__ __nv_bfloat16 g_ohi[(size_t)MROWS*NCOLS]; // attn-out split, bf16
__device__ __nv_bfloat16 g_olo[(size_t)MROWS*NCOLS];
__device__ __nv_bfloat16 g_wthi[(size_t)4*DD*NCOLS]; // 4 transposed weights [N,K], bf16 hi
__device__ __nv_bfloat16 g_wtlo[(size_t)4*DD*NCOLS]; // lo

// ---------------- helpers ----------------
__device__ __forceinline__ uint32_t smem_u32(const void* p) {
    uint32_t a;
    asm("{ .reg .u64 t; cvta.to.shared.u64 t, %1; cvt.u32.u64 %0, t; }" : "=r"(a) : "l"(p));
    return a;
}
__device__ __forceinline__ float tf32_rna(float v) {
    uint32_t r;
    asm("cvt.rna.tf32.f32 %0, %1;" : "=r"(r) : "f"(v));
    return __uint_as_float(r);
}
__device__ __forceinline__ uint32_t f2b(float v) { return __float_as_uint(v); }
// pack two f32 -> bf16x2 word, first arg in bits[15:0]
__device__ __forceinline__ uint32_t pack_bf16(float lo, float hi) {
    uint32_t r;
    asm("cvt.rn.bf16x2.f32 %0, %1, %2;" : "=r"(r) : "f"(hi), "f"(lo));
    return r;
}

__device__ __forceinline__ void cp16(uint32_t s, const void* g) {
    asm volatile("cp.async.cg.shared.global [%0], [%1], 16;" :: "r"(s), "l"(g));
}
__device__ __forceinline__ void cp_commit() { asm volatile("cp.async.commit_group;"); }
template<int N>
__device__ __forceinline__ void cp_wait() {
    asm volatile("cp.async.wait_group %0;" :: "n"(N) : "memory");
}

// mma.sync m16n8k8 tf32 (flash QK)
__device__ __forceinline__ void mma8(float* c, const uint32_t* a, const uint32_t* b) {
    asm volatile(
        "mma.sync.aligned.m16n8k8.row.col.f32.tf32.tf32.f32 "
        "{%0,%1,%2,%3}, {%4,%5,%6,%7}, {%8,%9}, {%0,%1,%2,%3};"
        : "+f"(c[0]), "+f"(c[1]), "+f"(c[2]), "+f"(c[3])
        : "r"(a[0]), "r"(a[1]), "r"(a[2]), "r"(a[3]), "r"(b[0]), "r"(b[1]));
}
// mma.sync m16n8k16 bf16 (GEMMs + flash PV)
__device__ __forceinline__ void mma16(float* c, const uint32_t* a, const uint32_t* b) {
    asm volatile(
        "mma.sync.aligned.m16n8k16.row.col.f32.bf16.bf16.f32 "
        "{%0,%1,%2,%3}, {%4,%5,%6,%7}, {%8,%9}, {%0,%1,%2,%3};"
        : "+f"(c[0]), "+f"(c[1]), "+f"(c[2]), "+f"(c[3])
        : "r"(a[0]), "r"(a[1]), "r"(a[2]), "r"(a[3]), "r"(b[0]), "r"(b[1]));
}

__device__ __forceinline__ void bf16_split(float v, __nv_bfloat16& h, __nv_bfloat16& l) {
    h = __float2bfloat16(v);
    l = __float2bfloat16(v - __bfloat162float(h));
}

// ---------------- prep kernels ----------------
struct alignas(8) bf16x4 { __nv_bfloat162 a, b; };

__global__ void __launch_bounds__(256) split_kernel(const float* __restrict__ in,
                                                    __nv_bfloat16* __restrict__ hi,
                                                    __nv_bfloat16* __restrict__ lo, int n4) {
    int i = blockIdx.x * blockDim.x + threadIdx.x;
    if (i < n4) {
        float4 v = ((const float4*)in)[i];
        __nv_bfloat16 h0, h1, h2, h3, l0, l1, l2, l3;
        bf16_split(v.x, h0, l0);
        bf16_split(v.y, h1, l1);
        bf16_split(v.z, h2, l2);
        bf16_split(v.w, h3, l3);
        bf16x4 H; H.a = __nv_bfloat162(h0, h1); H.b = __nv_bfloat162(h2, h3);
        bf16x4 L; L.a = __nv_bfloat162(l0, l1); L.b = __nv_bfloat162(l2, l3);
        ((bf16x4*)hi)[i] = H;
        ((bf16x4*)lo)[i] = L;
    }
}

// W [K=1024][N=1024] -> Wt hi/lo [N][K] bf16, 4 matrices via blockIdx.z
__global__ void __launch_bounds__(256) transpose_split_kernel(
    const float* __restrict__ w0, const float* __restrict__ w1,
    const float* __restrict__ w2, const float* __restrict__ w3,
    __nv_bfloat16* __restrict__ hi, __nv_bfloat16* __restrict__ lo)
{
    __shared__ float t[32][33];
    int z = blockIdx.z;
    const float* W = (z == 0) ? w0 : (z == 1) ? w1 : (z == 2) ? w2 : w3;
    __nv_bfloat16* H = hi + (size_t)z * DD * NCOLS;
    __nv_bfloat16* L = lo + (size_t)z * DD * NCOLS;
    int tx = threadIdx.x & 31, ty = threadIdx.x >> 5;
    int n0 = blockIdx.x * 32, k0 = blockIdx.y * 32;
#pragma unroll
    for (int i = 0; i < 4; i++)
        t[ty + i * 8][tx] = W[(size_t)(k0 + ty + i * 8) * NCOLS + n0 + tx];
    __syncthreads();
#pragma unroll
    for (int i = 0; i < 4; i++) {
        float v = t[tx][ty + i * 8];
        __nv_bfloat16 h, l;
        bf16_split(v, h, l);
        size_t o = (size_t)(n0 + ty + i * 8) * DD + k0 + tx;
        H[o] = h;
        L[o] = l;
    }
}

// ---------------- bf16x3 GEMM core: tile 128x64, warp 32x32 ----------------
// LDS.64 fragment loads via logical-k remap (thread qd takes words 2qd,2qd+1).
#define BK2 32
#define BSTRW 20                   // 32-bit words per smem row
#define ATILE_W (128*BSTRW)        // 2560 words
#define BTILE_W (64*BSTRW)         // 1280 words
#define GEMM_SMEM ((2*2*ATILE_W + 2*2*BTILE_W)*4)   // 61440 bytes
#define WSZ ((size_t)DD*NCOLS)

__device__ __forceinline__ void gemm_core(
    const __nv_bfloat16* __restrict__ Ahi, const __nv_bfloat16* __restrict__ Alo,
    const __nv_bfloat16* __restrict__ Bhi, const __nv_bfloat16* __restrict__ Blo,
    int Kdim, int bm, int bn, float c[2][4][4])
{
    extern __shared__ uint32_t smw[];
    uint32_t* sAH = smw;
    uint32_t* sAL = smw + 2 * ATILE_W;
    uint32_t* sBH = smw + 4 * ATILE_W;
    uint32_t* sBL = smw + 4 * ATILE_W + 2 * BTILE_W;
    const uint32_t uAH = smem_u32(sAH), uAL = smem_u32(sAL);
    const uint32_t uBH = smem_u32(sBH), uBL = smem_u32(sBL);

    const int tid = threadIdx.x, lane = tid & 31, wid = tid >> 5;
    const int grp = lane >> 2, qd = lane & 3;
    const int wm = (wid >> 1) << 5, wn = (wid & 1) << 5;

#pragma unroll
    for (int i = 0; i < 2; i++)
#pragma unroll
        for (int j = 0; j < 4; j++)
#pragma unroll
            for (int r = 0; r < 4; r++) c[i][j][r] = 0.0f;

    const int NKB = Kdim / BK2;

    auto load_stage = [&](int kb, int st) {
        int koff = kb * BK2;
#pragma unroll
        for (int i = 0; i < 2; i++) {
            int ch = i * 256 + tid;
            int row = ch >> 2, seg = ch & 3;
            size_t gA = (size_t)(bm + row) * Kdim + koff + seg * 8;
            uint32_t so = (st * ATILE_W + row * BSTRW + seg * 4) * 4;
            cp16(uAH + so, Ahi + gA);
            cp16(uAL + so, Alo + gA);
        }
        {
            int row = tid >> 2, seg = tid & 3;
            size_t gB = (size_t)(bn + row) * Kdim + koff + seg * 8;
            uint32_t so = (st * BTILE_W + row * BSTRW + seg * 4) * 4;
            cp16(uBH + so, Bhi + gB);
            cp16(uBL + so, Blo + gB);
        }
        cp_commit();
    };

    load_stage(0, 0);
    for (int kb = 0; kb < NKB; kb++) {
        int st = kb & 1;
        if (kb + 1 < NKB) { load_stage(kb + 1, st ^ 1); cp_wait<1>(); }
        else               { cp_wait<0>(); }
        __syncthreads();

        const uint32_t* AH = sAH + st * ATILE_W;
        const uint32_t* AL = sAL + st * ATILE_W;
        const uint32_t* BH = sBH + st * BTILE_W;
        const uint32_t* BL = sBL + st * BTILE_W;

#pragma unroll
        for (int ks = 0; ks < 2; ks++) {
            const int kw = ks * 8 + 2 * qd;      // LDS.64 pair base
            uint32_t ah[2][4], bh[4][2];
#pragma unroll
            for (int mt = 0; mt < 2; mt++) {
                const uint32_t* p = AH + (wm + mt * 16 + grp) * BSTRW + kw;
                uint2 v0 = *(const uint2*)p;
                uint2 v1 = *(const uint2*)(p + 8 * BSTRW);
                ah[mt][0] = v0.x; ah[mt][2] = v0.y;
                ah[mt][1] = v1.x; ah[mt][3] = v1.y;
            }
#pragma unroll
            for (int nt = 0; nt < 4; nt++) {
                uint2 vb = *(const uint2*)(BH + (wn + nt * 8 + grp) * BSTRW + kw);
                bh[nt][0] = vb.x; bh[nt][1] = vb.y;
            }
#pragma unroll
            for (int mt = 0; mt < 2; mt++)
#pragma unroll
                for (int nt = 0; nt < 4; nt++) mma16(c[mt][nt], ah[mt], bh[nt]);

            // pass 2: ah * bl
            {
                uint32_t bl[4][2];
#pragma unroll
                for (int nt = 0; nt < 4; nt++) {
                    uint2 vb = *(const uint2*)(BL + (wn + nt * 8 + grp) * BSTRW + kw);
                    bl[nt][0] = vb.x; bl[nt][1] = vb.y;
                }
#pragma unroll
                for (int mt = 0; mt < 2; mt++)
#pragma unroll
                    for (int nt = 0; nt < 4; nt++) mma16(c[mt][nt], ah[mt], bl[nt]);
            }
            // pass 3: al * bh
            {
                uint32_t al[2][4];
#pragma unroll
                for (int mt = 0; mt < 2; mt++) {
                    const uint32_t* p = AL + (wm + mt * 16 + grp) * BSTRW + kw;
                    uint2 v0 = *(const uint2*)p;
                    uint2 v1 = *(const uint2*)(p + 8 * BSTRW);
                    al[mt][0] = v0.x; al[mt][2] = v0.y;
                    al[mt][1] = v1.x; al[mt][3] = v1.y;
                }
#pragma unroll
                for (int mt = 0; mt < 2; mt++)
#pragma unroll
                    for (int nt = 0; nt < 4; nt++) mma16(c[mt][nt], al[mt], bh[nt]);
            }
        }
        __syncthreads();
    }
}

// merged Q/K/V projection: gridDim.z = 3
__global__ void __launch_bounds__(256, 2) gemm_qkv(
    const __nv_bfloat16* __restrict__ xhi, const __nv_bfloat16* __restrict__ xlo,
    const __nv_bfloat16* __restrict__ wthi, const __nv_bfloat16* __restrict__ wtlo,
    const float* __restrict__ bq, const float* __restrict__ bk, const float* __restrict__ bv,
    float* __restrict__ gq, float* __restrict__ gk,
    __nv_bfloat16* __restrict__ vh, __nv_bfloat16* __restrict__ vl)
{
    const int z = blockIdx.z;
    const int bm = blockIdx.y << 7, bn = blockIdx.x << 6;
    const float* bias = (z == 0) ? bq : (z == 1) ? bk : bv;
    const float scale = (z == 0) ? 0.125f : 1.0f;

    float c[2][4][4];
    gemm_core(xhi, xlo, wthi + (size_t)z * WSZ, wtlo + (size_t)z * WSZ, DD, bm, bn, c);

    const int lane = threadIdx.x & 31, wid = threadIdx.x >> 5;
    const int grp = lane >> 2, qd = lane & 3;
    const int wm = (wid >> 1) << 5, wn = (wid & 1) << 5;
    float* C = (z == 0) ? gq : gk;

#pragma unroll
    for (int mt = 0; mt < 2; mt++) {
#pragma unroll
        for (int nt = 0; nt < 4; nt++) {
            int n = bn + wn + nt * 8 + 2 * qd;
            float b0v = bias[n], b1v = bias[n + 1];
#pragma unroll
            for (int rr = 0; rr < 2; rr++) {
                int m = bm + wm + mt * 16 + grp + rr * 8;
                float v0 = (c[mt][nt][rr * 2 + 0] + b0v) * scale;
                float v1 = (c[mt][nt][rr * 2 + 1] + b1v) * scale;
                int b_ = m >> 11, s = m & 2047;
                int h = n >> 6, hd = n & 63;
                if (z < 2) {
                    float2 o = make_float2(tf32_rna(v0), tf32_rna(v1));
                    *(float2*)&C[((size_t)(b_ * HH + h) * SS + s) * HDD + hd] = o;
                } else {
                    size_t off = ((size_t)((b_ * HH + h) * HDD + hd)) * SS + s;
                    __nv_bfloat16 hh0, ll0, hh1, ll1;
                    bf16_split(v0, hh0, ll0);
                    bf16_split(v1, hh1, ll1);
                    vh[off] = hh0;       vl[off] = ll0;
                    vh[off + SS] = hh1;  vl[off + SS] = ll1;
                }
            }
        }
    }
}

// O projection: plain row-major f32 output
__global__ void __launch_bounds__(256, 2) gemm_o(
    const __nv_bfloat16* __restrict__ ohi, const __nv_bfloat16* __restrict__ olo,
    const __nv_bfloat16* __restrict__ wthi, const __nv_bfloat16* __restrict__ wtlo,
    const float* __restrict__ bias, float* __restrict__ C)
{
    const int bm = blockIdx.y << 7, bn = blockIdx.x << 6;
    float c[2][4][4];
    gemm_core(ohi, olo, wthi, wtlo, NCOLS, bm, bn, c);

    const int lane = threadIdx.x & 31, wid = threadIdx.x >> 5;
    const int grp = lane >> 2, qd = lane & 3;
    const int wm = (wid >> 1) << 5, wn = (wid & 1) << 5;
#pragma unroll
    for (int mt = 0; mt < 2; mt++) {
#pragma unroll
        for (int nt = 0; nt < 4; nt++) {
            int n = bn + wn + nt * 8 + 2 * qd;
            float b0v = bias[n], b1v = bias[n + 1];
#pragma unroll
            for (int rr = 0; rr < 2; rr++) {
                int m = bm + wm + mt * 16 + grp + rr * 8;
                float v0 = c[mt][nt][rr * 2 + 0] + b0v;
                float v1 = c[mt][nt][rr * 2 + 1] + b1v;
                *(float2*)&C[(size_t)m * NCOLS + n] = make_float2(v0, v1);
            }
        }
    }
}

// ---------------- flash attention: QK tf32, PV bf16x3, LDS.64 frags ----------------
#define QSTR 68
#define KSTR 68
#define VSTW 36
#define PSTW 36
#define QOFF 0
#define KOFF  (128*QSTR)
#define VHOFF (KOFF + 2*64*KSTR)
#define VLOFF (VHOFF + 2*64*VSTW)
#define PHOFF (VLOFF + 2*64*VSTW)
#define PLOFF (PHOFF + 128*PSTW)
#define FLASH_WORDS (PLOFF + 128*PSTW)
#define FLASH_SMEM (FLASH_WORDS*4)       // 143360 B

__global__ void __launch_bounds__(256) flash_kernel(
    const float* __restrict__ gq, const float* __restrict__ gk,
    const __nv_bfloat16* __restrict__ gvh, const __nv_bfloat16* __restrict__ gvl,
    float* __restrict__ go)
{
    extern __shared__ float smf[];
    uint32_t* smw = (uint32_t*)smf;
    const uint32_t sb = smem_u32(smf);

    const int tid = threadIdx.x, lane = tid & 31, wid = tid >> 5;
    const int grp = lane >> 2, qd = lane & 3;
    const int qt = blockIdx.x;
    const int bh = blockIdx.y;

    const float* Qg = gq  + ((size_t)bh * SS + qt * 128) * HDD;
    const float* Kg = gk  + (size_t)bh * SS * HDD;
    const __nv_bfloat16* Vh = gvh + (size_t)bh * HDD * SS;
    const __nv_bfloat16* Vl = gvl + (size_t)bh * HDD * SS;

#pragma unroll
    for (int i = 0; i < 8; i++) {
        int ch = i * 256 + tid;
        int row = ch >> 4, seg = ch & 15;
        cp16(sb + (QOFF + row * QSTR) * 4 + seg * 16, Qg + row * 64 + seg * 4);
    }
    auto load_kv = [&](int kt, int st) {
#pragma unroll
        for (int i = 0; i < 4; i++) {
            int ch = i * 256 + tid;
            int row = ch >> 4, seg = ch & 15;
            cp16(sb + (KOFF + st * 64 * KSTR + row * KSTR) * 4 + seg * 16,
                 Kg + (size_t)(kt * 64 + row) * 64 + seg * 4);
        }
#pragma unroll
        for (int i = 0; i < 2; i++) {
            int ch = i * 256 + tid;
            int row = ch >> 3, seg = ch & 7;
            size_t g = (size_t)row * SS + kt * 64 + seg * 8;
            cp16(sb + (VHOFF + st * 64 * VSTW + row * VSTW + seg * 4) * 4, Vh + g);
            cp16(sb + (VLOFF + st * 64 * VSTW + row * VSTW + seg * 4) * 4, Vl + g);
        }
        cp_commit();
    };
    load_kv(0, 0);

    float co[8][4];
#pragma unroll
    for (int i = 0; i < 8; i++)
#pragma unroll
        for (int r = 0; r < 4; r++) co[i][r] = 0.0f;
    float m0 = -1e30f, m1 = -1e30f, l0 = 0.0f, l1 = 0.0f;

    const int r0 = wid * 16;
    const float* Qrow = smf + QOFF + (r0 + grp) * QSTR;
    uint32_t* PhW = smw + PHOFF + (r0 + grp) * PSTW;
    uint32_t* PlW = smw + PLOFF + (r0 + grp) * PSTW;

    for (int kt = 0; kt < SS / 64; kt++) {
        const int st = kt & 1;
        __syncthreads();
        if (kt + 1 < SS / 64) { load_kv(kt + 1, st ^ 1); cp_wait<1>(); }
        else                   { cp_wait<0>(); }
        __syncthreads();

        const float*    Kb  = smf + KOFF + st * 64 * KSTR;
        const uint32_t* VhB = smw + VHOFF + st * 64 * VSTW;
        const uint32_t* VlB = smw + VLOFF + st * 64 * VSTW;

        // ---- S = Q K^T (tf32; logical d remap: thread qd takes d = 8ks+2qd, +1)
        float cs[8][4];
#pragma unroll
        for (int i = 0; i < 8; i++)
#pragma unroll
            for (int r = 0; r < 4; r++) cs[i][r] = 0.0f;
#pragma unroll
        for (int ks = 0; ks < 8; ks++) {
            const int d = ks * 8 + 2 * qd;
            uint32_t a[4];
            uint2 qa0 = *(const uint2*)(Qrow + d);
            uint2 qa1 = *(const uint2*)(Qrow + 8 * QSTR + d);
            a[0] = qa0.x; a[2] = qa0.y;
            a[1] = qa1.x; a[3] = qa1.y;
#pragma unroll
            for (int nt = 0; nt < 8; nt++) {
                uint2 bb = *(const uint2*)(Kb + (nt * 8 + grp) * KSTR + d);
                uint32_t b[2];
                b[0] = bb.x; b[1] = bb.y;
                mma8(cs[nt], a, b);
            }
        }

        // ---- online softmax; P stored bf16 hi/lo packed
        float mx0 = -1e30f, mx1 = -1e30f;
#pragma unroll
        for (int nt = 0; nt < 8; nt++) {
            mx0 = fmaxf(mx0, fmaxf(cs[nt][0], cs[nt][1]));
            mx1 = fmaxf(mx1, fmaxf(cs[nt][2], cs[nt][3]));
        }
        mx0 = fmaxf(mx0, __shfl_xor_sync(0xffffffffu, mx0, 1));
        mx0 = fmaxf(mx0, __shfl_xor_sync(0xffffffffu, mx0, 2));
        mx1 = fmaxf(mx1, __shfl_xor_sync(0xffffffffu, mx1, 1));
        mx1 = fmaxf(mx1, __shfl_xor_sync(0xffffffffu, mx1, 2));
        float mn0 = fmaxf(m0, mx0), mn1 = fmaxf(m1, mx1);
        float al0 = __expf(m0 - mn0), al1 = __expf(m1 - mn1);
        float s0 = 0.0f, s1 = 0.0f;
#pragma unroll
        for (int nt = 0; nt < 8; nt++) {
            float p0 = __expf(cs[nt][0] - mn0);
            float p1 = __expf(cs[nt][1] - mn0);
            float p2 = __expf(cs[nt][2] - mn1);
            float p3 = __expf(cs[nt][3] - mn1);
            s0 += p0 + p1;
            s1 += p2 + p3;
            uint32_t h01 = pack_bf16(p0, p1);
            float r0f = p0 - __uint_as_float(h01 << 16);
            float r1f = p1 - __uint_as_float(h01 & 0xFFFF0000u);
            PhW[nt * 4 + qd] = h01;
            PlW[nt * 4 + qd] = pack_bf16(r0f, r1f);
            uint32_t h23 = pack_bf16(p2, p3);
            float r2f = p2 - __uint_as_float(h23 << 16);
            float r3f = p3 - __uint_as_float(h23 & 0xFFFF0000u);
            PhW[8 * PSTW + nt * 4 + qd] = h23;
            PlW[8 * PSTW + nt * 4 + qd] = pack_bf16(r2f, r3f);
        }
        s0 += __shfl_xor_sync(0xffffffffu, s0, 1);
        s0 += __shfl_xor_sync(0xffffffffu, s0, 2);
        s1 += __shfl_xor_sync(0xffffffffu, s1, 1);
        s1 += __shfl_xor_sync(0xffffffffu, s1, 2);
        l0 = l0 * al0 + s0;
        l1 = l1 * al1 + s1;
        m0 = mn0;
        m1 = mn1;
#pragma unroll
        for (int nt = 0; nt < 8; nt++) {
            co[nt][0] *= al0; co[nt][1] *= al0;
            co[nt][2] *= al1; co[nt][3] *= al1;
        }
        __syncwarp();

        // ---- O += P V (bf16x3; logical key-word remap: thread qd -> words 2qd,2qd+1)
#pragma unroll
        for (int ks2 = 0; ks2 < 4; ks2++) {
            const int kw = ks2 * 8 + 2 * qd;
            uint32_t aH[4], aL[4];
            uint2 h0 = *(const uint2*)(PhW + kw);
            uint2 h1 = *(const uint2*)(PhW + 8 * PSTW + kw);
            aH[0] = h0.x; aH[2] = h0.y; aH[1] = h1.x; aH[3] = h1.y;
            uint2 l0v = *(const uint2*)(PlW + kw);
            uint2 l1v = *(const uint2*)(PlW + 8 * PSTW + kw);
            aL[0] = l0v.x; aL[2] = l0v.y; aL[1] = l1v.x; aL[3] = l1v.y;
#pragma unroll
            for (int nt = 0; nt < 8; nt++) {
                uint32_t b[2];
                uint2 vb = *(const uint2*)(VhB + (nt * 8 + grp) * VSTW + kw);
                b[0] = vb.x; b[1] = vb.y;
                mma16(co[nt], aH, b);
                mma16(co[nt], aL, b);
                uint2 vl2 = *(const uint2*)(VlB + (nt * 8 + grp) * VSTW + kw);
                b[0] = vl2.x; b[1] = vl2.y;
                mma16(co[nt], aH, b);
            }
        }
        __syncwarp();
    }

    const int b_ = bh >> 4;
    const int h  = bh & 15;
    const float inv0 = 1.0f / l0, inv1 = 1.0f / l1;
    const int q0 = qt * 128 + r0 + grp;
#pragma unroll
    for (int nt = 0; nt < 8; nt++) {
        int n = nt * 8 + 2 * qd;
        *(float2*)&go[((size_t)(b_ * SS + q0) * HH + h) * HDD + n] =
            make_float2(co[nt][0] * inv0, co[nt][1] * inv0);
        *(float2*)&go[((size_t)(b_ * SS + q0 + 8) * HH + h) * HDD + n] =
            make_float2(co[nt][2] * inv1, co[nt][3] * inv1);
    }
}

// ---------------------------------------------------------------------------
extern "C" void kernel_launch(void* const* d_in, const int* in_sizes, int n_in,
                              void* d_out, int out_size)
{
    const float* x  = (const float*)d_in[0];
    const float* wq = (const float*)d_in[1];
    const float* bq = (const float*)d_in[2];
    const float* wk = (const float*)d_in[3];
    const float* bk = (const float*)d_in[4];
    const float* wv = (const float*)d_in[5];
    const float* bv = (const float*)d_in[6];
    const float* wo = (const float*)d_in[7];
    const float* bo = (const float*)d_in[8];
    float* out = (float*)d_out;

    float *gq, *gk, *go;
    __nv_bfloat16 *gvh, *gvl, *xhi, *xlo, *ohi, *olo, *wthi, *wtlo;
    cudaGetSymbolAddress((void**)&gq,   g_q);
    cudaGetSymbolAddress((void**)&gk,   g_k);
    cudaGetSymbolAddress((void**)&gvh,  g_vhi);
    cudaGetSymbolAddress((void**)&gvl,  g_vlo);
    cudaGetSymbolAddress((void**)&go,   g_o);
    cudaGetSymbolAddress((void**)&xhi,  g_xhi);
    cudaGetSymbolAddress((void**)&xlo,  g_xlo);
    cudaGetSymbolAddress((void**)&ohi,  g_ohi);
    cudaGetSymbolAddress((void**)&olo,  g_olo);
    cudaGetSymbolAddress((void**)&wthi, g_wthi);
    cudaGetSymbolAddress((void**)&wtlo, g_wtlo);

    cudaFuncSetAttribute(gemm_qkv, cudaFuncAttributeMaxDynamicSharedMemorySize, GEMM_SMEM);
    cudaFuncSetAttribute(gemm_o,   cudaFuncAttributeMaxDynamicSharedMemorySize, GEMM_SMEM);
    cudaFuncSetAttribute(flash_kernel, cudaFuncAttributeMaxDynamicSharedMemorySize, FLASH_SMEM);

    // prep
    split_kernel<<<(MROWS * DD / 4 + 255) / 256, 256>>>(x, xhi, xlo, MROWS * DD / 4);
    transpose_split_kernel<<<dim3(NCOLS / 32, DD / 32, 4), 256>>>(wq, wk, wv, wo, wthi, wtlo);

    gemm_qkv<<<dim3(NCOLS / 64, MROWS / 128, 3), 256, GEMM_SMEM>>>(
        xhi, xlo, wthi, wtlo, bq, bk, bv, gq, gk, gvh, gvl);

    flash_kernel<<<dim3(SS / 128, BB * HH), 256, FLASH_SMEM>>>(gq, gk, gvh, gvl, go);

    split_kernel<<<(MROWS * NCOLS / 4 + 255) / 256, 256>>>(go, ohi, olo, MROWS * NCOLS / 4);
    gemm_o<<<dim3(NCOLS / 64, MROWS / 128), 256, GEMM_SMEM>>>(
        ohi, olo, wthi + 3 * WSZ, wtlo + 3 * WSZ, bo, out);
}

// round 11
// speedup vs baseline: 1.3127x; 1.3127x over previous
#include <cuda_runtime.h>
#include <cuda_bf16.h>
#include <cstdint>

#define BB 2
#define SS 2048
#define DD 1024
#define HH 16
#define HDD 64
#define MROWS (BB*SS)    // 4096
#define NCOLS (HH*HDD)   // 1024

// ---------------- scratch (__device__ globals; allocation-free rule) ----------------
__device__ float g_q  [(size_t)MROWS*NCOLS];  // [B,H,S,HD], tf32-rounded, pre-scaled 1/8
__device__ float g_k  [(size_t)MROWS*NCOLS];  // [B,H,S,HD], tf32-rounded
__device__ __nv_bfloat16 g_vhi[(size_t)MROWS*NCOLS]; // V^T [B,H,HD,S] bf16 hi
__device__ __nv_bfloat16 g_vlo[(size_t)MROWS*NCOLS]; // V^T bf16 lo
__device__ float g_o  [(size_t)MROWS*NCOLS];  // [B,S,H*HD] attention out
__device__ __nv_bfloat16 g_xhi[(size_t)MROWS*DD];    // x split, bf16
__device__ __nv_bfloat16 g_xlo[(size_t)MROWS*DD];
__device__ __nv_bfloat16 g_ohi[(size_t)MROWS*NCOLS]; // attn-out split, bf16
__device__ __nv_bfloat16 g_olo[(size_t)MROWS*NCOLS];
__device__ __nv_bfloat16 g_wthi[(size_t)4*DD*NCOLS]; // 4 transposed weights [N,K], bf16 hi
__device__ __nv_bfloat16 g_wtlo[(size_t)4*DD*NCOLS]; // lo

// ---------------- helpers ----------------
__device__ __forceinline__ uint32_t smem_u32(const void* p) {
    uint32_t a;
    asm("{ .reg .u64 t; cvta.to.shared.u64 t, %1; cvt.u32.u64 %0, t; }" : "=r"(a) : "l"(p));
    return a;
}
__device__ __forceinline__ float tf32_rna(float v) {
    uint32_t r;
    asm("cvt.rna.tf32.f32 %0, %1;" : "=r"(r) : "f"(v));
    return __uint_as_float(r);
}
__device__ __forceinline__ uint32_t f2b(float v) { return __float_as_uint(v); }
// pack two f32 -> bf16x2 word, first arg in bits[15:0]
__device__ __forceinline__ uint32_t pack_bf16(float lo, float hi) {
    uint32_t r;
    asm("cvt.rn.bf16x2.f32 %0, %1, %2;" : "=r"(r) : "f"(hi), "f"(lo));
    return r;
}

__device__ __forceinline__ void cp16(uint32_t s, const void* g) {
    asm volatile("cp.async.cg.shared.global [%0], [%1], 16;" :: "r"(s), "l"(g));
}
__device__ __forceinline__ void cp_commit() { asm volatile("cp.async.commit_group;"); }
template<int N>
__device__ __forceinline__ void cp_wait() {
    asm volatile("cp.async.wait_group %0;" :: "n"(N) : "memory");
}

// mma.sync m16n8k8 tf32 (flash QK)
__device__ __forceinline__ void mma8(float* c, const uint32_t* a, const uint32_t* b) {
    asm volatile(
        "mma.sync.aligned.m16n8k8.row.col.f32.tf32.tf32.f32 "
        "{%0,%1,%2,%3}, {%4,%5,%6,%7}, {%8,%9}, {%0,%1,%2,%3};"
        : "+f"(c[0]), "+f"(c[1]), "+f"(c[2]), "+f"(c[3])
        : "r"(a[0]), "r"(a[1]), "r"(a[2]), "r"(a[3]), "r"(b[0]), "r"(b[1]));
}
// mma.sync m16n8k16 bf16 (GEMMs + flash PV)
__device__ __forceinline__ void mma16(float* c, const uint32_t* a, const uint32_t* b) {
    asm volatile(
        "mma.sync.aligned.m16n8k16.row.col.f32.bf16.bf16.f32 "
        "{%0,%1,%2,%3}, {%4,%5,%6,%7}, {%8,%9}, {%0,%1,%2,%3};"
        : "+f"(c[0]), "+f"(c[1]), "+f"(c[2]), "+f"(c[3])
        : "r"(a[0]), "r"(a[1]), "r"(a[2]), "r"(a[3]), "r"(b[0]), "r"(b[1]));
}

__device__ __forceinline__ void bf16_split(float v, __nv_bfloat16& h, __nv_bfloat16& l) {
    h = __float2bfloat16(v);
    l = __float2bfloat16(v - __bfloat162float(h));
}

// ---------------- prep kernels ----------------
struct alignas(8) bf16x4 { __nv_bfloat162 a, b; };

__global__ void __launch_bounds__(256) split_kernel(const float* __restrict__ in,
                                                    __nv_bfloat16* __restrict__ hi,
                                                    __nv_bfloat16* __restrict__ lo, int n4) {
    int i = blockIdx.x * blockDim.x + threadIdx.x;
    if (i < n4) {
        float4 v = ((const float4*)in)[i];
        __nv_bfloat16 h0, h1, h2, h3, l0, l1, l2, l3;
        bf16_split(v.x, h0, l0);
        bf16_split(v.y, h1, l1);
        bf16_split(v.z, h2, l2);
        bf16_split(v.w, h3, l3);
        bf16x4 H; H.a = __nv_bfloat162(h0, h1); H.b = __nv_bfloat162(h2, h3);
        bf16x4 L; L.a = __nv_bfloat162(l0, l1); L.b = __nv_bfloat162(l2, l3);
        ((bf16x4*)hi)[i] = H;
        ((bf16x4*)lo)[i] = L;
    }
}

// W [K=1024][N=1024] -> Wt hi/lo [N][K] bf16, 4 matrices via blockIdx.z
__global__ void __launch_bounds__(256) transpose_split_kernel(
    const float* __restrict__ w0, const float* __restrict__ w1,
    const float* __restrict__ w2, const float* __restrict__ w3,
    __nv_bfloat16* __restrict__ hi, __nv_bfloat16* __restrict__ lo)
{
    __shared__ float t[32][33];
    int z = blockIdx.z;
    const float* W = (z == 0) ? w0 : (z == 1) ? w1 : (z == 2) ? w2 : w3;
    __nv_bfloat16* H = hi + (size_t)z * DD * NCOLS;
    __nv_bfloat16* L = lo + (size_t)z * DD * NCOLS;
    int tx = threadIdx.x & 31, ty = threadIdx.x >> 5;
    int n0 = blockIdx.x * 32, k0 = blockIdx.y * 32;
#pragma unroll
    for (int i = 0; i < 4; i++)
        t[ty + i * 8][tx] = W[(size_t)(k0 + ty + i * 8) * NCOLS + n0 + tx];
    __syncthreads();
#pragma unroll
    for (int i = 0; i < 4; i++) {
        float v = t[tx][ty + i * 8];
        __nv_bfloat16 h, l;
        bf16_split(v, h, l);
        size_t o = (size_t)(n0 + ty + i * 8) * DD + k0 + tx;
        H[o] = h;
        L[o] = l;
    }
}

// ---------------- bf16x3 GEMM core: tile 128x64, warp 32x32 ----------------
// LDS.64 fragment loads; BSTRW=24 => bank-pair (grp*12+qd)%16 distinct: conflict-free.
#define BK2 32
#define BSTRW 24                   // 32-bit words per smem row (stride fixed for LDS.64)
#define ATILE_W (128*BSTRW)        // 3072 words
#define BTILE_W (64*BSTRW)         // 1536 words
#define GEMM_SMEM ((2*2*ATILE_W + 2*2*BTILE_W)*4)   // 73728 bytes
#define WSZ ((size_t)DD*NCOLS)

__device__ __forceinline__ void gemm_core(
    const __nv_bfloat16* __restrict__ Ahi, const __nv_bfloat16* __restrict__ Alo,
    const __nv_bfloat16* __restrict__ Bhi, const __nv_bfloat16* __restrict__ Blo,
    int Kdim, int bm, int bn, float c[2][4][4])
{
    extern __shared__ uint32_t smw[];
    uint32_t* sAH = smw;
    uint32_t* sAL = smw + 2 * ATILE_W;
    uint32_t* sBH = smw + 4 * ATILE_W;
    uint32_t* sBL = smw + 4 * ATILE_W + 2 * BTILE_W;
    const uint32_t uAH = smem_u32(sAH), uAL = smem_u32(sAL);
    const uint32_t uBH = smem_u32(sBH), uBL = smem_u32(sBL);

    const int tid = threadIdx.x, lane = tid & 31, wid = tid >> 5;
    const int grp = lane >> 2, qd = lane & 3;
    const int wm = (wid >> 1) << 5, wn = (wid & 1) << 5;

#pragma unroll
    for (int i = 0; i < 2; i++)
#pragma unroll
        for (int j = 0; j < 4; j++)
#pragma unroll
            for (int r = 0; r < 4; r++) c[i][j][r] = 0.0f;

    const int NKB = Kdim / BK2;

    auto load_stage = [&](int kb, int st) {
        int koff = kb * BK2;
#pragma unroll
        for (int i = 0; i < 2; i++) {
            int ch = i * 256 + tid;
            int row = ch >> 2, seg = ch & 3;
            size_t gA = (size_t)(bm + row) * Kdim + koff + seg * 8;
            uint32_t so = (st * ATILE_W + row * BSTRW + seg * 4) * 4;
            cp16(uAH + so, Ahi + gA);
            cp16(uAL + so, Alo + gA);
        }
        {
            int row = tid >> 2, seg = tid & 3;
            size_t gB = (size_t)(bn + row) * Kdim + koff + seg * 8;
            uint32_t so = (st * BTILE_W + row * BSTRW + seg * 4) * 4;
            cp16(uBH + so, Bhi + gB);
            cp16(uBL + so, Blo + gB);
        }
        cp_commit();
    };

    load_stage(0, 0);
    for (int kb = 0; kb < NKB; kb++) {
        int st = kb & 1;
        if (kb + 1 < NKB) { load_stage(kb + 1, st ^ 1); cp_wait<1>(); }
        else               { cp_wait<0>(); }
        __syncthreads();

        const uint32_t* AH = sAH + st * ATILE_W;
        const uint32_t* AL = sAL + st * ATILE_W;
        const uint32_t* BH = sBH + st * BTILE_W;
        const uint32_t* BL = sBL + st * BTILE_W;

#pragma unroll
        for (int ks = 0; ks < 2; ks++) {
            const int kw = ks * 8 + 2 * qd;      // LDS.64 pair base
            uint32_t ah[2][4], bh[4][2];
#pragma unroll
            for (int mt = 0; mt < 2; mt++) {
                const uint32_t* p = AH + (wm + mt * 16 + grp) * BSTRW + kw;
                uint2 v0 = *(const uint2*)p;
                uint2 v1 = *(const uint2*)(p + 8 * BSTRW);
                ah[mt][0] = v0.x; ah[mt][2] = v0.y;
                ah[mt][1] = v1.x; ah[mt][3] = v1.y;
            }
#pragma unroll
            for (int nt = 0; nt < 4; nt++) {
                uint2 vb = *(const uint2*)(BH + (wn + nt * 8 + grp) * BSTRW + kw);
                bh[nt][0] = vb.x; bh[nt][1] = vb.y;
            }
#pragma unroll
            for (int mt = 0; mt < 2; mt++)
#pragma unroll
                for (int nt = 0; nt < 4; nt++) mma16(c[mt][nt], ah[mt], bh[nt]);

            // pass 2: ah * bl
            {
                uint32_t bl[4][2];
#pragma unroll
                for (int nt = 0; nt < 4; nt++) {
                    uint2 vb = *(const uint2*)(BL + (wn + nt * 8 + grp) * BSTRW + kw);
                    bl[nt][0] = vb.x; bl[nt][1] = vb.y;
                }
#pragma unroll
                for (int mt = 0; mt < 2; mt++)
#pragma unroll
                    for (int nt = 0; nt < 4; nt++) mma16(c[mt][nt], ah[mt], bl[nt]);
            }
            // pass 3: al * bh
            {
                uint32_t al[2][4];
#pragma unroll
                for (int mt = 0; mt < 2; mt++) {
                    const uint32_t* p = AL + (wm + mt * 16 + grp) * BSTRW + kw;
                    uint2 v0 = *(const uint2*)p;
                    uint2 v1 = *(const uint2*)(p + 8 * BSTRW);
                    al[mt][0] = v0.x; al[mt][2] = v0.y;
                    al[mt][1] = v1.x; al[mt][3] = v1.y;
                }
#pragma unroll
                for (int mt = 0; mt < 2; mt++)
#pragma unroll
                    for (int nt = 0; nt < 4; nt++) mma16(c[mt][nt], al[mt], bh[nt]);
            }
        }
        __syncthreads();
    }
}

// merged Q/K/V projection: gridDim.z = 3
__global__ void __launch_bounds__(256, 2) gemm_qkv(
    const __nv_bfloat16* __restrict__ xhi, const __nv_bfloat16* __restrict__ xlo,
    const __nv_bfloat16* __restrict__ wthi, const __nv_bfloat16* __restrict__ wtlo,
    const float* __restrict__ bq, const float* __restrict__ bk, const float* __restrict__ bv,
    float* __restrict__ gq, float* __restrict__ gk,
    __nv_bfloat16* __restrict__ vh, __nv_bfloat16* __restrict__ vl)
{
    const int z = blockIdx.z;
    const int bm = blockIdx.y << 7, bn = blockIdx.x << 6;
    const float* bias = (z == 0) ? bq : (z == 1) ? bk : bv;
    const float scale = (z == 0) ? 0.125f : 1.0f;

    float c[2][4][4];
    gemm_core(xhi, xlo, wthi + (size_t)z * WSZ, wtlo + (size_t)z * WSZ, DD, bm, bn, c);

    const int lane = threadIdx.x & 31, wid = threadIdx.x >> 5;
    const int grp = lane >> 2, qd = lane & 3;
    const int wm = (wid >> 1) << 5, wn = (wid & 1) << 5;
    float* C = (z == 0) ? gq : gk;

#pragma unroll
    for (int mt = 0; mt < 2; mt++) {
#pragma unroll
        for (int nt = 0; nt < 4; nt++) {
            int n = bn + wn + nt * 8 + 2 * qd;
            float b0v = bias[n], b1v = bias[n + 1];
#pragma unroll
            for (int rr = 0; rr < 2; rr++) {
                int m = bm + wm + mt * 16 + grp + rr * 8;
                float v0 = (c[mt][nt][rr * 2 + 0] + b0v) * scale;
                float v1 = (c[mt][nt][rr * 2 + 1] + b1v) * scale;
                int b_ = m >> 11, s = m & 2047;
                int h = n >> 6, hd = n & 63;
                if (z < 2) {
                    float2 o = make_float2(tf32_rna(v0), tf32_rna(v1));
                    *(float2*)&C[((size_t)(b_ * HH + h) * SS + s) * HDD + hd] = o;
                } else {
                    size_t off = ((size_t)((b_ * HH + h) * HDD + hd)) * SS + s;
                    __nv_bfloat16 hh0, ll0, hh1, ll1;
                    bf16_split(v0, hh0, ll0);
                    bf16_split(v1, hh1, ll1);
                    vh[off] = hh0;       vl[off] = ll0;
                    vh[off + SS] = hh1;  vl[off + SS] = ll1;
                }
            }
        }
    }
}

// O projection: plain row-major f32 output
__global__ void __launch_bounds__(256, 2) gemm_o(
    const __nv_bfloat16* __restrict__ ohi, const __nv_bfloat16* __restrict__ olo,
    const __nv_bfloat16* __restrict__ wthi, const __nv_bfloat16* __restrict__ wtlo,
    const float* __restrict__ bias, float* __restrict__ C)
{
    const int bm = blockIdx.y << 7, bn = blockIdx.x << 6;
    float c[2][4][4];
    gemm_core(ohi, olo, wthi, wtlo, NCOLS, bm, bn, c);

    const int lane = threadIdx.x & 31, wid = threadIdx.x >> 5;
    const int grp = lane >> 2, qd = lane & 3;
    const int wm = (wid >> 1) << 5, wn = (wid & 1) << 5;
#pragma unroll
    for (int mt = 0; mt < 2; mt++) {
#pragma unroll
        for (int nt = 0; nt < 4; nt++) {
            int n = bn + wn + nt * 8 + 2 * qd;
            float b0v = bias[n], b1v = bias[n + 1];
#pragma unroll
            for (int rr = 0; rr < 2; rr++) {
                int m = bm + wm + mt * 16 + grp + rr * 8;
                float v0 = c[mt][nt][rr * 2 + 0] + b0v;
                float v1 = c[mt][nt][rr * 2 + 1] + b1v;
                *(float2*)&C[(size_t)m * NCOLS + n] = make_float2(v0, v1);
            }
        }
    }
}

// ---------------- flash attention: QK tf32, PV bf16x3, conflict-free LDS.64 ----------------
// QSTR/KSTR=72 f32 words ((72/2)%16=4 -> conflict-free); VSTW/PSTW=40 u32 words ((40/2)%16=4).
#define QSTR 72
#define KSTR 72
#define VSTW 40
#define PSTW 40
#define QOFF 0                           // 128*72 = 9216 words
#define KOFF  (128*QSTR)                 // 9216
#define VHOFF (KOFF + 2*64*KSTR)         // 18432
#define VLOFF (VHOFF + 2*64*VSTW)        // 23552
#define PHOFF (VLOFF + 2*64*VSTW)        // 28672
#define PLOFF (PHOFF + 128*PSTW)         // 33792
#define FLASH_WORDS (PLOFF + 128*PSTW)   // 38912
#define FLASH_SMEM (FLASH_WORDS*4)       // 155648 B

__global__ void __launch_bounds__(256) flash_kernel(
    const float* __restrict__ gq, const float* __restrict__ gk,
    const __nv_bfloat16* __restrict__ gvh, const __nv_bfloat16* __restrict__ gvl,
    float* __restrict__ go)
{
    extern __shared__ float smf[];
    uint32_t* smw = (uint32_t*)smf;
    const uint32_t sb = smem_u32(smf);

    const int tid = threadIdx.x, lane = tid & 31, wid = tid >> 5;
    const int grp = lane >> 2, qd = lane & 3;
    const int qt = blockIdx.x;
    const int bh = blockIdx.y;

    const float* Qg = gq  + ((size_t)bh * SS + qt * 128) * HDD;
    const float* Kg = gk  + (size_t)bh * SS * HDD;
    const __nv_bfloat16* Vh = gvh + (size_t)bh * HDD * SS;
    const __nv_bfloat16* Vl = gvl + (size_t)bh * HDD * SS;

#pragma unroll
    for (int i = 0; i < 8; i++) {
        int ch = i * 256 + tid;
        int row = ch >> 4, seg = ch & 15;
        cp16(sb + (QOFF + row * QSTR) * 4 + seg * 16, Qg + row * 64 + seg * 4);
    }
    auto load_kv = [&](int kt, int st) {
#pragma unroll
        for (int i = 0; i < 4; i++) {
            int ch = i * 256 + tid;
            int row = ch >> 4, seg = ch & 15;
            cp16(sb + (KOFF + st * 64 * KSTR + row * KSTR) * 4 + seg * 16,
                 Kg + (size_t)(kt * 64 + row) * 64 + seg * 4);
        }
#pragma unroll
        for (int i = 0; i < 2; i++) {
            int ch = i * 256 + tid;
            int row = ch >> 3, seg = ch & 7;
            size_t g = (size_t)row * SS + kt * 64 + seg * 8;
            cp16(sb + (VHOFF + st * 64 * VSTW + row * VSTW + seg * 4) * 4, Vh + g);
            cp16(sb + (VLOFF + st * 64 * VSTW + row * VSTW + seg * 4) * 4, Vl + g);
        }
        cp_commit();
    };
    load_kv(0, 0);

    float co[8][4];
#pragma unroll
    for (int i = 0; i < 8; i++)
#pragma unroll
        for (int r = 0; r < 4; r++) co[i][r] = 0.0f;
    float m0 = -1e30f, m1 = -1e30f, l0 = 0.0f, l1 = 0.0f;

    const int r0 = wid * 16;
    const float* Qrow = smf + QOFF + (r0 + grp) * QSTR;
    uint32_t* PhW = smw + PHOFF + (r0 + grp) * PSTW;
    uint32_t* PlW = smw + PLOFF + (r0 + grp) * PSTW;

    for (int kt = 0; kt < SS / 64; kt++) {
        const int st = kt & 1;
        __syncthreads();
        if (kt + 1 < SS / 64) { load_kv(kt + 1, st ^ 1); cp_wait<1>(); }
        else                   { cp_wait<0>(); }
        __syncthreads();

        const float*    Kb  = smf + KOFF + st * 64 * KSTR;
        const uint32_t* VhB = smw + VHOFF + st * 64 * VSTW;
        const uint32_t* VlB = smw + VLOFF + st * 64 * VSTW;

        // ---- S = Q K^T (tf32; logical d remap: thread qd takes d = 8ks+2qd, +1)
        float cs[8][4];
#pragma unroll
        for (int i = 0; i < 8; i++)
#pragma unroll
            for (int r = 0; r < 4; r++) cs[i][r] = 0.0f;
#pragma unroll
        for (int ks = 0; ks < 8; ks++) {
            const int d = ks * 8 + 2 * qd;
            uint32_t a[4];
            uint2 qa0 = *(const uint2*)(Qrow + d);
            uint2 qa1 = *(const uint2*)(Qrow + 8 * QSTR + d);
            a[0] = qa0.x; a[2] = qa0.y;
            a[1] = qa1.x; a[3] = qa1.y;
#pragma unroll
            for (int nt = 0; nt < 8; nt++) {
                uint2 bb = *(const uint2*)(Kb + (nt * 8 + grp) * KSTR + d);
                uint32_t b[2];
                b[0] = bb.x; b[1] = bb.y;
                mma8(cs[nt], a, b);
            }
        }

        // ---- online softmax; P stored bf16 hi/lo packed
        float mx0 = -1e30f, mx1 = -1e30f;
#pragma unroll
        for (int nt = 0; nt < 8; nt++) {
            mx0 = fmaxf(mx0, fmaxf(cs[nt][0], cs[nt][1]));
            mx1 = fmaxf(mx1, fmaxf(cs[nt][2], cs[nt][3]));
        }
        mx0 = fmaxf(mx0, __shfl_xor_sync(0xffffffffu, mx0, 1));
        mx0 = fmaxf(mx0, __shfl_xor_sync(0xffffffffu, mx0, 2));
        mx1 = fmaxf(mx1, __shfl_xor_sync(0xffffffffu, mx1, 1));
        mx1 = fmaxf(mx1, __shfl_xor_sync(0xffffffffu, mx1, 2));
        float mn0 = fmaxf(m0, mx0), mn1 = fmaxf(m1, mx1);
        float al0 = __expf(m0 - mn0), al1 = __expf(m1 - mn1);
        float s0 = 0.0f, s1 = 0.0f;
#pragma unroll
        for (int nt = 0; nt < 8; nt++) {
            float p0 = __expf(cs[nt][0] - mn0);
            float p1 = __expf(cs[nt][1] - mn0);
            float p2 = __expf(cs[nt][2] - mn1);
            float p3 = __expf(cs[nt][3] - mn1);
            s0 += p0 + p1;
            s1 += p2 + p3;
            uint32_t h01 = pack_bf16(p0, p1);
            float r0f = p0 - __uint_as_float(h01 << 16);
            float r1f = p1 - __uint_as_float(h01 & 0xFFFF0000u);
            PhW[nt * 4 + qd] = h01;
            PlW[nt * 4 + qd] = pack_bf16(r0f, r1f);
            uint32_t h23 = pack_bf16(p2, p3);
            float r2f = p2 - __uint_as_float(h23 << 16);
            float r3f = p3 - __uint_as_float(h23 & 0xFFFF0000u);
            PhW[8 * PSTW + nt * 4 + qd] = h23;
            PlW[8 * PSTW + nt * 4 + qd] = pack_bf16(r2f, r3f);
        }
        s0 += __shfl_xor_sync(0xffffffffu, s0, 1);
        s0 += __shfl_xor_sync(0xffffffffu, s0, 2);
        s1 += __shfl_xor_sync(0xffffffffu, s1, 1);
        s1 += __shfl_xor_sync(0xffffffffu, s1, 2);
        l0 = l0 * al0 + s0;
        l1 = l1 * al1 + s1;
        m0 = mn0;
        m1 = mn1;
#pragma unroll
        for (int nt = 0; nt < 8; nt++) {
            co[nt][0] *= al0; co[nt][1] *= al0;
            co[nt][2] *= al1; co[nt][3] *= al1;
        }
        __syncwarp();

        // ---- O += P V (bf16x3; logical key-word remap: thread qd -> words 2qd,2qd+1)
#pragma unroll
        for (int ks2 = 0; ks2 < 4; ks2++) {
            const int kw = ks2 * 8 + 2 * qd;
            uint32_t aH[4], aL[4];
            uint2 h0 = *(const uint2*)(PhW + kw);
            uint2 h1 = *(const uint2*)(PhW + 8 * PSTW + kw);
            aH[0] = h0.x; aH[2] = h0.y; aH[1] = h1.x; aH[3] = h1.y;
            uint2 l0v = *(const uint2*)(PlW + kw);
            uint2 l1v = *(const uint2*)(PlW + 8 * PSTW + kw);
            aL[0] = l0v.x; aL[2] = l0v.y; aL[1] = l1v.x; aL[3] = l1v.y;
#pragma unroll
            for (int nt = 0; nt < 8; nt++) {
                uint32_t b[2];
                uint2 vb = *(const uint2*)(VhB + (nt * 8 + grp) * VSTW + kw);
                b[0] = vb.x; b[1] = vb.y;
                mma16(co[nt], aH, b);
                mma16(co[nt], aL, b);
                uint2 vl2 = *(const uint2*)(VlB + (nt * 8 + grp) * VSTW + kw);
                b[0] = vl2.x; b[1] = vl2.y;
                mma16(co[nt], aH, b);
            }
        }
        __syncwarp();
    }

    const int b_ = bh >> 4;
    const int h  = bh & 15;
    const float inv0 = 1.0f / l0, inv1 = 1.0f / l1;
    const int q0 = qt * 128 + r0 + grp;
#pragma unroll
    for (int nt = 0; nt < 8; nt++) {
        int n = nt * 8 + 2 * qd;
        *(float2*)&go[((size_t)(b_ * SS + q0) * HH + h) * HDD + n] =
            make_float2(co[nt][0] * inv0, co[nt][1] * inv0);
        *(float2*)&go[((size_t)(b_ * SS + q0 + 8) * HH + h) * HDD + n] =
            make_float2(co[nt][2] * inv1, co[nt][3] * inv1);
    }
}

// ---------------------------------------------------------------------------
extern "C" void kernel_launch(void* const* d_in, const int* in_sizes, int n_in,
                              void* d_out, int out_size)
{
    const float* x  = (const float*)d_in[0];
    const float* wq = (const float*)d_in[1];
    const float* bq = (const float*)d_in[2];
    const float* wk = (const float*)d_in[3];
    const float* bk = (const float*)d_in[4];
    const float* wv = (const float*)d_in[5];
    const float* bv = (const float*)d_in[6];
    const float* wo = (const float*)d_in[7];
    const float* bo = (const float*)d_in[8];
    float* out = (float*)d_out;

    float *gq, *gk, *go;
    __nv_bfloat16 *gvh, *gvl, *xhi, *xlo, *ohi, *olo, *wthi, *wtlo;
    cudaGetSymbolAddress((void**)&gq,   g_q);
    cudaGetSymbolAddress((void**)&gk,   g_k);
    cudaGetSymbolAddress((void**)&gvh,  g_vhi);
    cudaGetSymbolAddress((void**)&gvl,  g_vlo);
    cudaGetSymbolAddress((void**)&go,   g_o);
    cudaGetSymbolAddress((void**)&xhi,  g_xhi);
    cudaGetSymbolAddress((void**)&xlo,  g_xlo);
    cudaGetSymbolAddress((void**)&ohi,  g_ohi);
    cudaGetSymbolAddress((void**)&olo,  g_olo);
    cudaGetSymbolAddress((void**)&wthi, g_wthi);
    cudaGetSymbolAddress((void**)&wtlo, g_wtlo);

    cudaFuncSetAttribute(gemm_qkv, cudaFuncAttributeMaxDynamicSharedMemorySize, GEMM_SMEM);
    cudaFuncSetAttribute(gemm_o,   cudaFuncAttributeMaxDynamicSharedMemorySize, GEMM_SMEM);
    cudaFuncSetAttribute(flash_kernel, cudaFuncAttributeMaxDynamicSharedMemorySize, FLASH_SMEM);

    // prep
    split_kernel<<<(MROWS * DD / 4 + 255) / 256, 256>>>(x, xhi, xlo, MROWS * DD / 4);
    transpose_split_kernel<<<dim3(NCOLS / 32, DD / 32, 4), 256>>>(wq, wk, wv, wo, wthi, wtlo);

    gemm_qkv<<<dim3(NCOLS / 64, MROWS / 128, 3), 256, GEMM_SMEM>>>(
        xhi, xlo, wthi, wtlo, bq, bk, bv, gq, gk, gvh, gvl);

    flash_kernel<<<dim3(SS / 128, BB * HH), 256, FLASH_SMEM>>>(gq, gk, gvh, gvl, go);

    split_kernel<<<(MROWS * NCOLS / 4 + 255) / 256, 256>>>(go, ohi, olo, MROWS * NCOLS / 4);
    gemm_o<<<dim3(NCOLS / 64, MROWS / 128), 256, GEMM_SMEM>>>(
        ohi, olo, wthi + 3 * WSZ, wtlo + 3 * WSZ, bo, out);
}

// round 12
// speedup vs baseline: 1.4551x; 1.1084x over previous
#include <cuda_runtime.h>
#include <cuda_bf16.h>
#include <cstdint>

#define BB 2
#define SS 2048
#define DD 1024
#define HH 16
#define HDD 64
#define MROWS (BB*SS)    // 4096
#define NCOLS (HH*HDD)   // 1024

// ---------------- scratch (__device__ globals; allocation-free rule) ----------------
__device__ float g_q  [(size_t)MROWS*NCOLS];  // [B,H,S,HD], tf32-rounded, pre-scaled 1/8
__device__ float g_k  [(size_t)MROWS*NCOLS];  // [B,H,S,HD], tf32-rounded
__device__ __nv_bfloat16 g_vhi[(size_t)MROWS*NCOLS]; // V^T [B,H,HD,S] bf16 hi
__device__ __nv_bfloat16 g_vlo[(size_t)MROWS*NCOLS]; // V^T bf16 lo
__device__ float g_o  [(size_t)MROWS*NCOLS];  // [B,S,H*HD] attention out
__device__ __nv_bfloat16 g_xhi[(size_t)MROWS*DD];    // x split, bf16
__device__ __nv_bfloat16 g_xlo[(size_t)MROWS*DD];
__device__ __nv_bfloat16 g_ohi[(size_t)MROWS*NCOLS]; // attn-out split, bf16
__device__ __nv_bfloat16 g_olo[(size_t)MROWS*NCOLS];
__device__ __nv_bfloat16 g_wthi[(size_t)4*DD*NCOLS]; // 4 transposed weights [N,K], bf16 hi
__device__ __nv_bfloat16 g_wtlo[(size_t)4*DD*NCOLS]; // lo

// ---------------- helpers ----------------
__device__ __forceinline__ uint32_t smem_u32(const void* p) {
    uint32_t a;
    asm("{ .reg .u64 t; cvta.to.shared.u64 t, %1; cvt.u32.u64 %0, t; }" : "=r"(a) : "l"(p));
    return a;
}
__device__ __forceinline__ float tf32_rna(float v) {
    uint32_t r;
    asm("cvt.rna.tf32.f32 %0, %1;" : "=r"(r) : "f"(v));
    return __uint_as_float(r);
}
__device__ __forceinline__ uint32_t f2b(float v) { return __float_as_uint(v); }
// pack two f32 -> bf16x2 word, first arg in bits[15:0]
__device__ __forceinline__ uint32_t pack_bf16(float lo, float hi) {
    uint32_t r;
    asm("cvt.rn.bf16x2.f32 %0, %1, %2;" : "=r"(r) : "f"(hi), "f"(lo));
    return r;
}

__device__ __forceinline__ void cp16(uint32_t s, const void* g) {
    asm volatile("cp.async.cg.shared.global [%0], [%1], 16;" :: "r"(s), "l"(g));
}
__device__ __forceinline__ void cp_commit() { asm volatile("cp.async.commit_group;"); }
template<int N>
__device__ __forceinline__ void cp_wait() {
    asm volatile("cp.async.wait_group %0;" :: "n"(N) : "memory");
}

// mma.sync m16n8k8 tf32 (flash QK)
__device__ __forceinline__ void mma8(float* c, const uint32_t* a, const uint32_t* b) {
    asm volatile(
        "mma.sync.aligned.m16n8k8.row.col.f32.tf32.tf32.f32 "
        "{%0,%1,%2,%3}, {%4,%5,%6,%7}, {%8,%9}, {%0,%1,%2,%3};"
        : "+f"(c[0]), "+f"(c[1]), "+f"(c[2]), "+f"(c[3])
        : "r"(a[0]), "r"(a[1]), "r"(a[2]), "r"(a[3]), "r"(b[0]), "r"(b[1]));
}
// mma.sync m16n8k16 bf16 (GEMMs + flash PV)
__device__ __forceinline__ void mma16(float* c, const uint32_t* a, const uint32_t* b) {
    asm volatile(
        "mma.sync.aligned.m16n8k16.row.col.f32.bf16.bf16.f32 "
        "{%0,%1,%2,%3}, {%4,%5,%6,%7}, {%8,%9}, {%0,%1,%2,%3};"
        : "+f"(c[0]), "+f"(c[1]), "+f"(c[2]), "+f"(c[3])
        : "r"(a[0]), "r"(a[1]), "r"(a[2]), "r"(a[3]), "r"(b[0]), "r"(b[1]));
}

__device__ __forceinline__ void bf16_split(float v, __nv_bfloat16& h, __nv_bfloat16& l) {
    h = __float2bfloat16(v);
    l = __float2bfloat16(v - __bfloat162float(h));
}

// ---------------- prep kernels ----------------
struct alignas(8) bf16x4 { __nv_bfloat162 a, b; };

__global__ void __launch_bounds__(256) split_kernel(const float* __restrict__ in,
                                                    __nv_bfloat16* __restrict__ hi,
                                                    __nv_bfloat16* __restrict__ lo, int n4) {
    int i = blockIdx.x * blockDim.x + threadIdx.x;
    if (i < n4) {
        float4 v = ((const float4*)in)[i];
        __nv_bfloat16 h0, h1, h2, h3, l0, l1, l2, l3;
        bf16_split(v.x, h0, l0);
        bf16_split(v.y, h1, l1);
        bf16_split(v.z, h2, l2);
        bf16_split(v.w, h3, l3);
        bf16x4 H; H.a = __nv_bfloat162(h0, h1); H.b = __nv_bfloat162(h2, h3);
        bf16x4 L; L.a = __nv_bfloat162(l0, l1); L.b = __nv_bfloat162(l2, l3);
        ((bf16x4*)hi)[i] = H;
        ((bf16x4*)lo)[i] = L;
    }
}

// W [K=1024][N=1024] -> Wt hi/lo [N][K] bf16, 4 matrices via blockIdx.z
__global__ void __launch_bounds__(256) transpose_split_kernel(
    const float* __restrict__ w0, const float* __restrict__ w1,
    const float* __restrict__ w2, const float* __restrict__ w3,
    __nv_bfloat16* __restrict__ hi, __nv_bfloat16* __restrict__ lo)
{
    __shared__ float t[32][33];
    int z = blockIdx.z;
    const float* W = (z == 0) ? w0 : (z == 1) ? w1 : (z == 2) ? w2 : w3;
    __nv_bfloat16* H = hi + (size_t)z * DD * NCOLS;
    __nv_bfloat16* L = lo + (size_t)z * DD * NCOLS;
    int tx = threadIdx.x & 31, ty = threadIdx.x >> 5;
    int n0 = blockIdx.x * 32, k0 = blockIdx.y * 32;
#pragma unroll
    for (int i = 0; i < 4; i++)
        t[ty + i * 8][tx] = W[(size_t)(k0 + ty + i * 8) * NCOLS + n0 + tx];
    __syncthreads();
#pragma unroll
    for (int i = 0; i < 4; i++) {
        float v = t[tx][ty + i * 8];
        __nv_bfloat16 h, l;
        bf16_split(v, h, l);
        size_t o = (size_t)(n0 + ty + i * 8) * DD + k0 + tx;
        H[o] = h;
        L[o] = l;
    }
}

// ---------------- bf16x3 GEMM core: tile 128x64, warp 32x32 (unchanged from R11) ----------------
#define BK2 32
#define BSTRW 24
#define ATILE_W (128*BSTRW)
#define BTILE_W (64*BSTRW)
#define GEMM_SMEM ((2*2*ATILE_W + 2*2*BTILE_W)*4)   // 73728 bytes
#define WSZ ((size_t)DD*NCOLS)

__device__ __forceinline__ void gemm_core(
    const __nv_bfloat16* __restrict__ Ahi, const __nv_bfloat16* __restrict__ Alo,
    const __nv_bfloat16* __restrict__ Bhi, const __nv_bfloat16* __restrict__ Blo,
    int Kdim, int bm, int bn, float c[2][4][4])
{
    extern __shared__ uint32_t smw[];
    uint32_t* sAH = smw;
    uint32_t* sAL = smw + 2 * ATILE_W;
    uint32_t* sBH = smw + 4 * ATILE_W;
    uint32_t* sBL = smw + 4 * ATILE_W + 2 * BTILE_W;
    const uint32_t uAH = smem_u32(sAH), uAL = smem_u32(sAL);
    const uint32_t uBH = smem_u32(sBH), uBL = smem_u32(sBL);

    const int tid = threadIdx.x, lane = tid & 31, wid = tid >> 5;
    const int grp = lane >> 2, qd = lane & 3;
    const int wm = (wid >> 1) << 5, wn = (wid & 1) << 5;

#pragma unroll
    for (int i = 0; i < 2; i++)
#pragma unroll
        for (int j = 0; j < 4; j++)
#pragma unroll
            for (int r = 0; r < 4; r++) c[i][j][r] = 0.0f;

    const int NKB = Kdim / BK2;

    auto load_stage = [&](int kb, int st) {
        int koff = kb * BK2;
#pragma unroll
        for (int i = 0; i < 2; i++) {
            int ch = i * 256 + tid;
            int row = ch >> 2, seg = ch & 3;
            size_t gA = (size_t)(bm + row) * Kdim + koff + seg * 8;
            uint32_t so = (st * ATILE_W + row * BSTRW + seg * 4) * 4;
            cp16(uAH + so, Ahi + gA);
            cp16(uAL + so, Alo + gA);
        }
        {
            int row = tid >> 2, seg = tid & 3;
            size_t gB = (size_t)(bn + row) * Kdim + koff + seg * 8;
            uint32_t so = (st * BTILE_W + row * BSTRW + seg * 4) * 4;
            cp16(uBH + so, Bhi + gB);
            cp16(uBL + so, Blo + gB);
        }
        cp_commit();
    };

    load_stage(0, 0);
    for (int kb = 0; kb < NKB; kb++) {
        int st = kb & 1;
        if (kb + 1 < NKB) { load_stage(kb + 1, st ^ 1); cp_wait<1>(); }
        else               { cp_wait<0>(); }
        __syncthreads();

        const uint32_t* AH = sAH + st * ATILE_W;
        const uint32_t* AL = sAL + st * ATILE_W;
        const uint32_t* BH = sBH + st * BTILE_W;
        const uint32_t* BL = sBL + st * BTILE_W;

#pragma unroll
        for (int ks = 0; ks < 2; ks++) {
            const int kw = ks * 8 + 2 * qd;
            uint32_t ah[2][4], bh[4][2];
#pragma unroll
            for (int mt = 0; mt < 2; mt++) {
                const uint32_t* p = AH + (wm + mt * 16 + grp) * BSTRW + kw;
                uint2 v0 = *(const uint2*)p;
                uint2 v1 = *(const uint2*)(p + 8 * BSTRW);
                ah[mt][0] = v0.x; ah[mt][2] = v0.y;
                ah[mt][1] = v1.x; ah[mt][3] = v1.y;
            }
#pragma unroll
            for (int nt = 0; nt < 4; nt++) {
                uint2 vb = *(const uint2*)(BH + (wn + nt * 8 + grp) * BSTRW + kw);
                bh[nt][0] = vb.x; bh[nt][1] = vb.y;
            }
#pragma unroll
            for (int mt = 0; mt < 2; mt++)
#pragma unroll
                for (int nt = 0; nt < 4; nt++) mma16(c[mt][nt], ah[mt], bh[nt]);

            {
                uint32_t bl[4][2];
#pragma unroll
                for (int nt = 0; nt < 4; nt++) {
                    uint2 vb = *(const uint2*)(BL + (wn + nt * 8 + grp) * BSTRW + kw);
                    bl[nt][0] = vb.x; bl[nt][1] = vb.y;
                }
#pragma unroll
                for (int mt = 0; mt < 2; mt++)
#pragma unroll
                    for (int nt = 0; nt < 4; nt++) mma16(c[mt][nt], ah[mt], bl[nt]);
            }
            {
                uint32_t al[2][4];
#pragma unroll
                for (int mt = 0; mt < 2; mt++) {
                    const uint32_t* p = AL + (wm + mt * 16 + grp) * BSTRW + kw;
                    uint2 v0 = *(const uint2*)p;
                    uint2 v1 = *(const uint2*)(p + 8 * BSTRW);
                    al[mt][0] = v0.x; al[mt][2] = v0.y;
                    al[mt][1] = v1.x; al[mt][3] = v1.y;
                }
#pragma unroll
                for (int mt = 0; mt < 2; mt++)
#pragma unroll
                    for (int nt = 0; nt < 4; nt++) mma16(c[mt][nt], al[mt], bh[nt]);
            }
        }
        __syncthreads();
    }
}

// merged Q/K/V projection: gridDim.z = 3
__global__ void __launch_bounds__(256, 2) gemm_qkv(
    const __nv_bfloat16* __restrict__ xhi, const __nv_bfloat16* __restrict__ xlo,
    const __nv_bfloat16* __restrict__ wthi, const __nv_bfloat16* __restrict__ wtlo,
    const float* __restrict__ bq, const float* __restrict__ bk, const float* __restrict__ bv,
    float* __restrict__ gq, float* __restrict__ gk,
    __nv_bfloat16* __restrict__ vh, __nv_bfloat16* __restrict__ vl)
{
    const int z = blockIdx.z;
    const int bm = blockIdx.y << 7, bn = blockIdx.x << 6;
    const float* bias = (z == 0) ? bq : (z == 1) ? bk : bv;
    const float scale = (z == 0) ? 0.125f : 1.0f;

    float c[2][4][4];
    gemm_core(xhi, xlo, wthi + (size_t)z * WSZ, wtlo + (size_t)z * WSZ, DD, bm, bn, c);

    const int lane = threadIdx.x & 31, wid = threadIdx.x >> 5;
    const int grp = lane >> 2, qd = lane & 3;
    const int wm = (wid >> 1) << 5, wn = (wid & 1) << 5;
    float* C = (z == 0) ? gq : gk;

#pragma unroll
    for (int mt = 0; mt < 2; mt++) {
#pragma unroll
        for (int nt = 0; nt < 4; nt++) {
            int n = bn + wn + nt * 8 + 2 * qd;
            float b0v = bias[n], b1v = bias[n + 1];
#pragma unroll
            for (int rr = 0; rr < 2; rr++) {
                int m = bm + wm + mt * 16 + grp + rr * 8;
                float v0 = (c[mt][nt][rr * 2 + 0] + b0v) * scale;
                float v1 = (c[mt][nt][rr * 2 + 1] + b1v) * scale;
                int b_ = m >> 11, s = m & 2047;
                int h = n >> 6, hd = n & 63;
                if (z < 2) {
                    float2 o = make_float2(tf32_rna(v0), tf32_rna(v1));
                    *(float2*)&C[((size_t)(b_ * HH + h) * SS + s) * HDD + hd] = o;
                } else {
                    size_t off = ((size_t)((b_ * HH + h) * HDD + hd)) * SS + s;
                    __nv_bfloat16 hh0, ll0, hh1, ll1;
                    bf16_split(v0, hh0, ll0);
                    bf16_split(v1, hh1, ll1);
                    vh[off] = hh0;       vl[off] = ll0;
                    vh[off + SS] = hh1;  vl[off + SS] = ll1;
                }
            }
        }
    }
}

// O projection: plain row-major f32 output
__global__ void __launch_bounds__(256, 2) gemm_o(
    const __nv_bfloat16* __restrict__ ohi, const __nv_bfloat16* __restrict__ olo,
    const __nv_bfloat16* __restrict__ wthi, const __nv_bfloat16* __restrict__ wtlo,
    const float* __restrict__ bias, float* __restrict__ C)
{
    const int bm = blockIdx.y << 7, bn = blockIdx.x << 6;
    float c[2][4][4];
    gemm_core(ohi, olo, wthi, wtlo, NCOLS, bm, bn, c);

    const int lane = threadIdx.x & 31, wid = threadIdx.x >> 5;
    const int grp = lane >> 2, qd = lane & 3;
    const int wm = (wid >> 1) << 5, wn = (wid & 1) << 5;
#pragma unroll
    for (int mt = 0; mt < 2; mt++) {
#pragma unroll
        for (int nt = 0; nt < 4; nt++) {
            int n = bn + wn + nt * 8 + 2 * qd;
            float b0v = bias[n], b1v = bias[n + 1];
#pragma unroll
            for (int rr = 0; rr < 2; rr++) {
                int m = bm + wm + mt * 16 + grp + rr * 8;
                float v0 = c[mt][nt][rr * 2 + 0] + b0v;
                float v1 = c[mt][nt][rr * 2 + 1] + b1v;
                *(float2*)&C[(size_t)m * NCOLS + n] = make_float2(v0, v1);
            }
        }
    }
}

// ---------------- flash attention v3: QK tf32, PV bf16x3 with P-in-registers ----------------
// Q smem (72-stride), K single-stage smem, V 2-stage bf16 hi/lo (VSTW=36: (4grp+qd)%32
// conflict-free LDS.32). P never touches smem: score fragments are re-packed directly into
// PV A-fragments (m16n8 acc layout == m16n8k16 A layout over keys).
#define QSTR 72
#define KSTR 72
#define VSTW 36
#define QOFF 0                            // 9216 f32 words
#define KOFF  (128*QSTR)                  // 9216
#define VHOFF (KOFF + 64*KSTR)            // 13824 (u32 words; 2 stages x 64 x 36)
#define VLOFF (VHOFF + 2*64*VSTW)         // 18432
#define FLASH_WORDS (VLOFF + 2*64*VSTW)   // 23040
#define FLASH_SMEM (FLASH_WORDS*4)        // 92160 B -> 2 CTAs/SM

__global__ void __launch_bounds__(256, 2) flash_kernel(
    const float* __restrict__ gq, const float* __restrict__ gk,
    const __nv_bfloat16* __restrict__ gvh, const __nv_bfloat16* __restrict__ gvl,
    float* __restrict__ go)
{
    extern __shared__ float smf[];
    uint32_t* smw = (uint32_t*)smf;
    const uint32_t sb = smem_u32(smf);

    const int tid = threadIdx.x, lane = tid & 31, wid = tid >> 5;
    const int grp = lane >> 2, qd = lane & 3;
    const int qt = blockIdx.x;
    const int bh = blockIdx.y;

    const float* Qg = gq  + ((size_t)bh * SS + qt * 128) * HDD;
    const float* Kg = gk  + (size_t)bh * SS * HDD;
    const __nv_bfloat16* Vh = gvh + (size_t)bh * HDD * SS;
    const __nv_bfloat16* Vl = gvl + (size_t)bh * HDD * SS;

    auto load_kv = [&](int kt, int st) {
        // K: 64 rows x 64 f32 into the single K buffer
#pragma unroll
        for (int i = 0; i < 4; i++) {
            int ch = i * 256 + tid;
            int row = ch >> 4, seg = ch & 15;
            cp16(sb + (KOFF + row * KSTR) * 4 + seg * 16,
                 Kg + (size_t)(kt * 64 + row) * 64 + seg * 4);
        }
        // V^T: 64 d-rows x 64 keys bf16, stage st
#pragma unroll
        for (int i = 0; i < 2; i++) {
            int ch = i * 256 + tid;
            int row = ch >> 3, seg = ch & 7;
            size_t g = (size_t)row * SS + kt * 64 + seg * 8;
            cp16(sb + (VHOFF + st * 64 * VSTW + row * VSTW + seg * 4) * 4, Vh + g);
            cp16(sb + (VLOFF + st * 64 * VSTW + row * VSTW + seg * 4) * 4, Vl + g);
        }
        cp_commit();
    };

    // prologue: Q + first K/V
#pragma unroll
    for (int i = 0; i < 8; i++) {
        int ch = i * 256 + tid;
        int row = ch >> 4, seg = ch & 15;
        cp16(sb + (QOFF + row * QSTR) * 4 + seg * 16, Qg + row * 64 + seg * 4);
    }
    load_kv(0, 0);

    float co[8][4];
#pragma unroll
    for (int i = 0; i < 8; i++)
#pragma unroll
        for (int r = 0; r < 4; r++) co[i][r] = 0.0f;
    float m0 = -1e30f, m1 = -1e30f, l0 = 0.0f, l1 = 0.0f;

    const int r0 = wid * 16;
    const float* Qrow = smf + QOFF + (r0 + grp) * QSTR;
    const float* Kb = smf + KOFF;

    for (int kt = 0; kt < SS / 64; kt++) {
        const int st = kt & 1;
        cp_wait<0>();
        __syncthreads();                // K[kt] + V[kt] resident; prior reads done

        // ---- S = Q K^T (tf32; consistent logical-d remap, LDS.64 operands)
        float cs[8][4];
#pragma unroll
        for (int i = 0; i < 8; i++)
#pragma unroll
            for (int r = 0; r < 4; r++) cs[i][r] = 0.0f;
#pragma unroll
        for (int ks = 0; ks < 8; ks++) {
            const int d = ks * 8 + 2 * qd;
            uint32_t a[4];
            uint2 qa0 = *(const uint2*)(Qrow + d);
            uint2 qa1 = *(const uint2*)(Qrow + 8 * QSTR + d);
            a[0] = qa0.x; a[2] = qa0.y;
            a[1] = qa1.x; a[3] = qa1.y;
#pragma unroll
            for (int nt = 0; nt < 8; nt++) {
                uint2 bb = *(const uint2*)(Kb + (nt * 8 + grp) * KSTR + d);
                uint32_t b[2];
                b[0] = bb.x; b[1] = bb.y;
                mma8(cs[nt], a, b);
            }
        }

        __syncthreads();                // all warps done reading K[kt]
        if (kt + 1 < SS / 64) load_kv(kt + 1, st ^ 1);

        // ---- online softmax: row max
        float mx0 = -1e30f, mx1 = -1e30f;
#pragma unroll
        for (int nt = 0; nt < 8; nt++) {
            mx0 = fmaxf(mx0, fmaxf(cs[nt][0], cs[nt][1]));
            mx1 = fmaxf(mx1, fmaxf(cs[nt][2], cs[nt][3]));
        }
        mx0 = fmaxf(mx0, __shfl_xor_sync(0xffffffffu, mx0, 1));
        mx0 = fmaxf(mx0, __shfl_xor_sync(0xffffffffu, mx0, 2));
        mx1 = fmaxf(mx1, __shfl_xor_sync(0xffffffffu, mx1, 1));
        mx1 = fmaxf(mx1, __shfl_xor_sync(0xffffffffu, mx1, 2));
        float mn0 = fmaxf(m0, mx0), mn1 = fmaxf(m1, mx1);
        float al0 = __expf(m0 - mn0), al1 = __expf(m1 - mn1);
        m0 = mn0;
        m1 = mn1;
#pragma unroll
        for (int nt = 0; nt < 8; nt++) {
            co[nt][0] *= al0; co[nt][1] *= al0;
            co[nt][2] *= al1; co[nt][3] *= al1;
        }

        const uint32_t* VhB = smw + VHOFF + st * 64 * VSTW;
        const uint32_t* VlB = smw + VLOFF + st * 64 * VSTW;
        float s0 = 0.0f, s1 = 0.0f;

        // ---- fused exp + PV: per k16 step, build P fragments in registers
#pragma unroll
        for (int ks2 = 0; ks2 < 4; ks2++) {
            const int t0 = 2 * ks2, t1 = t0 + 1;
            float p00 = __expf(cs[t0][0] - mn0);
            float p01 = __expf(cs[t0][1] - mn0);
            float p02 = __expf(cs[t0][2] - mn1);
            float p03 = __expf(cs[t0][3] - mn1);
            float p10 = __expf(cs[t1][0] - mn0);
            float p11 = __expf(cs[t1][1] - mn0);
            float p12 = __expf(cs[t1][2] - mn1);
            float p13 = __expf(cs[t1][3] - mn1);
            s0 += (p00 + p01) + (p10 + p11);
            s1 += (p02 + p03) + (p12 + p13);

            uint32_t aH[4], aL[4];
            aH[0] = pack_bf16(p00, p01);
            aL[0] = pack_bf16(p00 - __uint_as_float(aH[0] << 16),
                              p01 - __uint_as_float(aH[0] & 0xFFFF0000u));
            aH[1] = pack_bf16(p02, p03);
            aL[1] = pack_bf16(p02 - __uint_as_float(aH[1] << 16),
                              p03 - __uint_as_float(aH[1] & 0xFFFF0000u));
            aH[2] = pack_bf16(p10, p11);
            aL[2] = pack_bf16(p10 - __uint_as_float(aH[2] << 16),
                              p11 - __uint_as_float(aH[2] & 0xFFFF0000u));
            aH[3] = pack_bf16(p12, p13);
            aL[3] = pack_bf16(p12 - __uint_as_float(aH[3] << 16),
                              p13 - __uint_as_float(aH[3] & 0xFFFF0000u));

            const int w0 = ks2 * 8 + qd;
#pragma unroll
            for (int nt = 0; nt < 8; nt++) {
                const uint32_t* vh2 = VhB + (nt * 8 + grp) * VSTW;
                uint32_t b[2];
                b[0] = vh2[w0];
                b[1] = vh2[w0 + 4];
                mma16(co[nt], aH, b);
                mma16(co[nt], aL, b);
                const uint32_t* vl2 = VlB + (nt * 8 + grp) * VSTW;
                b[0] = vl2[w0];
                b[1] = vl2[w0 + 4];
                mma16(co[nt], aH, b);
            }
        }

        s0 += __shfl_xor_sync(0xffffffffu, s0, 1);
        s0 += __shfl_xor_sync(0xffffffffu, s0, 2);
        s1 += __shfl_xor_sync(0xffffffffu, s1, 1);
        s1 += __shfl_xor_sync(0xffffffffu, s1, 2);
        l0 = l0 * al0 + s0;
        l1 = l1 * al1 + s1;
    }

    const int b_ = bh >> 4;
    const int h  = bh & 15;
    const float inv0 = 1.0f / l0, inv1 = 1.0f / l1;
    const int q0 = qt * 128 + r0 + grp;
#pragma unroll
    for (int nt = 0; nt < 8; nt++) {
        int n = nt * 8 + 2 * qd;
        *(float2*)&go[((size_t)(b_ * SS + q0) * HH + h) * HDD + n] =
            make_float2(co[nt][0] * inv0, co[nt][1] * inv0);
        *(float2*)&go[((size_t)(b_ * SS + q0 + 8) * HH + h) * HDD + n] =
            make_float2(co[nt][2] * inv1, co[nt][3] * inv1);
    }
}

// ---------------------------------------------------------------------------
extern "C" void kernel_launch(void* const* d_in, const int* in_sizes, int n_in,
                              void* d_out, int out_size)
{
    const float* x  = (const float*)d_in[0];
    const float* wq = (const float*)d_in[1];
    const float* bq = (const float*)d_in[2];
    const float* wk = (const float*)d_in[3];
    const float* bk = (const float*)d_in[4];
    const float* wv = (const float*)d_in[5];
    const float* bv = (const float*)d_in[6];
    const float* wo = (const float*)d_in[7];
    const float* bo = (const float*)d_in[8];
    float* out = (float*)d_out;

    float *gq, *gk, *go;
    __nv_bfloat16 *gvh, *gvl, *xhi, *xlo, *ohi, *olo, *wthi, *wtlo;
    cudaGetSymbolAddress((void**)&gq,   g_q);
    cudaGetSymbolAddress((void**)&gk,   g_k);
    cudaGetSymbolAddress((void**)&gvh,  g_vhi);
    cudaGetSymbolAddress((void**)&gvl,  g_vlo);
    cudaGetSymbolAddress((void**)&go,   g_o);
    cudaGetSymbolAddress((void**)&xhi,  g_xhi);
    cudaGetSymbolAddress((void**)&xlo,  g_xlo);
    cudaGetSymbolAddress((void**)&ohi,  g_ohi);
    cudaGetSymbolAddress((void**)&olo,  g_olo);
    cudaGetSymbolAddress((void**)&wthi, g_wthi);
    cudaGetSymbolAddress((void**)&wtlo, g_wtlo);

    cudaFuncSetAttribute(gemm_qkv, cudaFuncAttributeMaxDynamicSharedMemorySize, GEMM_SMEM);
    cudaFuncSetAttribute(gemm_o,   cudaFuncAttributeMaxDynamicSharedMemorySize, GEMM_SMEM);
    cudaFuncSetAttribute(flash_kernel, cudaFuncAttributeMaxDynamicSharedMemorySize, FLASH_SMEM);

    // prep
    split_kernel<<<(MROWS * DD / 4 + 255) / 256, 256>>>(x, xhi, xlo, MROWS * DD / 4);
    transpose_split_kernel<<<dim3(NCOLS / 32, DD / 32, 4), 256>>>(wq, wk, wv, wo, wthi, wtlo);

    gemm_qkv<<<dim3(NCOLS / 64, MROWS / 128, 3), 256, GEMM_SMEM>>>(
        xhi, xlo, wthi, wtlo, bq, bk, bv, gq, gk, gvh, gvl);

    flash_kernel<<<dim3(SS / 128, BB * HH), 256, FLASH_SMEM>>>(gq, gk, gvh, gvl, go);

    split_kernel<<<(MROWS * NCOLS / 4 + 255) / 256, 256>>>(go, ohi, olo, MROWS * NCOLS / 4);
    gemm_o<<<dim3(NCOLS / 64, MROWS / 128), 256, GEMM_SMEM>>>(
        ohi, olo, wthi + 3 * WSZ, wtlo + 3 * WSZ, bo, out);
}

// round 13
// speedup vs baseline: 1.4876x; 1.0223x over previous
#include <cuda_runtime.h>
#include <cuda_bf16.h>
#include <cuda_fp16.h>
#include <cstdint>

#define BB 2
#define SS 2048
#define DD 1024
#define HH 16
#define HDD 64
#define MROWS (BB*SS)    // 4096
#define NCOLS (HH*HDD)   // 1024

// ---------------- scratch (__device__ globals; allocation-free rule) ----------------
__device__ float g_q  [(size_t)MROWS*NCOLS];  // [B,H,S,HD], tf32-rounded, pre-scaled 1/8
__device__ float g_k  [(size_t)MROWS*NCOLS];  // [B,H,S,HD], tf32-rounded
__device__ __half g_vhi[(size_t)MROWS*NCOLS]; // V^T [B,H,HD,S] fp16 hi (key-word interleaved)
__device__ __half g_vlo[(size_t)MROWS*NCOLS]; // V^T fp16 lo
__device__ float g_o  [(size_t)MROWS*NCOLS];  // [B,S,H*HD] attention out
__device__ __nv_bfloat16 g_xhi[(size_t)MROWS*DD];    // x split, bf16
__device__ __nv_bfloat16 g_xlo[(size_t)MROWS*DD];
__device__ __nv_bfloat16 g_ohi[(size_t)MROWS*NCOLS]; // attn-out split, bf16
__device__ __nv_bfloat16 g_olo[(size_t)MROWS*NCOLS];
__device__ __nv_bfloat16 g_wthi[(size_t)4*DD*NCOLS]; // 4 transposed weights [N,K], bf16 hi
__device__ __nv_bfloat16 g_wtlo[(size_t)4*DD*NCOLS]; // lo

// ---------------- helpers ----------------
__device__ __forceinline__ uint32_t smem_u32(const void* p) {
    uint32_t a;
    asm("{ .reg .u64 t; cvta.to.shared.u64 t, %1; cvt.u32.u64 %0, t; }" : "=r"(a) : "l"(p));
    return a;
}
__device__ __forceinline__ float tf32_rna(float v) {
    uint32_t r;
    asm("cvt.rna.tf32.f32 %0, %1;" : "=r"(r) : "f"(v));
    return __uint_as_float(r);
}
__device__ __forceinline__ uint32_t f2b(float v) { return __float_as_uint(v); }
// pack two f32 -> f16x2 word, first arg in bits[15:0]
__device__ __forceinline__ uint32_t pack_f16(float lo, float hi) {
    uint32_t r;
    asm("cvt.rn.f16x2.f32 %0, %1, %2;" : "=r"(r) : "f"(hi), "f"(lo));
    return r;
}

__device__ __forceinline__ void cp16(uint32_t s, const void* g) {
    asm volatile("cp.async.cg.shared.global [%0], [%1], 16;" :: "r"(s), "l"(g));
}
__device__ __forceinline__ void cp_commit() { asm volatile("cp.async.commit_group;"); }
template<int N>
__device__ __forceinline__ void cp_wait() {
    asm volatile("cp.async.wait_group %0;" :: "n"(N) : "memory");
}

// mma.sync m16n8k8 tf32 (flash QK)
__device__ __forceinline__ void mma8(float* c, const uint32_t* a, const uint32_t* b) {
    asm volatile(
        "mma.sync.aligned.m16n8k8.row.col.f32.tf32.tf32.f32 "
        "{%0,%1,%2,%3}, {%4,%5,%6,%7}, {%8,%9}, {%0,%1,%2,%3};"
        : "+f"(c[0]), "+f"(c[1]), "+f"(c[2]), "+f"(c[3])
        : "r"(a[0]), "r"(a[1]), "r"(a[2]), "r"(a[3]), "r"(b[0]), "r"(b[1]));
}
// mma.sync m16n8k16 bf16 (GEMMs)
__device__ __forceinline__ void mma16(float* c, const uint32_t* a, const uint32_t* b) {
    asm volatile(
        "mma.sync.aligned.m16n8k16.row.col.f32.bf16.bf16.f32 "
        "{%0,%1,%2,%3}, {%4,%5,%6,%7}, {%8,%9}, {%0,%1,%2,%3};"
        : "+f"(c[0]), "+f"(c[1]), "+f"(c[2]), "+f"(c[3])
        : "r"(a[0]), "r"(a[1]), "r"(a[2]), "r"(a[3]), "r"(b[0]), "r"(b[1]));
}
// mma.sync m16n8k16 fp16 (flash PV)
__device__ __forceinline__ void mma16h(float* c, const uint32_t* a, const uint32_t* b) {
    asm volatile(
        "mma.sync.aligned.m16n8k16.row.col.f32.f16.f16.f32 "
        "{%0,%1,%2,%3}, {%4,%5,%6,%7}, {%8,%9}, {%0,%1,%2,%3};"
        : "+f"(c[0]), "+f"(c[1]), "+f"(c[2]), "+f"(c[3])
        : "r"(a[0]), "r"(a[1]), "r"(a[2]), "r"(a[3]), "r"(b[0]), "r"(b[1]));
}

__device__ __forceinline__ void bf16_split(float v, __nv_bfloat16& h, __nv_bfloat16& l) {
    h = __float2bfloat16(v);
    l = __float2bfloat16(v - __bfloat162float(h));
}
__device__ __forceinline__ void f16_split(float v, __half& h, __half& l) {
    h = __float2half_rn(v);
    l = __float2half_rn(v - __half2float(h));
}

// ---------------- prep kernels ----------------
struct alignas(8) bf16x4 { __nv_bfloat162 a, b; };

__global__ void __launch_bounds__(256) split_kernel(const float* __restrict__ in,
                                                    __nv_bfloat16* __restrict__ hi,
                                                    __nv_bfloat16* __restrict__ lo, int n4) {
    int i = blockIdx.x * blockDim.x + threadIdx.x;
    if (i < n4) {
        float4 v = ((const float4*)in)[i];
        __nv_bfloat16 h0, h1, h2, h3, l0, l1, l2, l3;
        bf16_split(v.x, h0, l0);
        bf16_split(v.y, h1, l1);
        bf16_split(v.z, h2, l2);
        bf16_split(v.w, h3, l3);
        bf16x4 H; H.a = __nv_bfloat162(h0, h1); H.b = __nv_bfloat162(h2, h3);
        bf16x4 L; L.a = __nv_bfloat162(l0, l1); L.b = __nv_bfloat162(l2, l3);
        ((bf16x4*)hi)[i] = H;
        ((bf16x4*)lo)[i] = L;
    }
}

// W [K=1024][N=1024] -> Wt hi/lo [N][K] bf16, 4 matrices via blockIdx.z
__global__ void __launch_bounds__(256) transpose_split_kernel(
    const float* __restrict__ w0, const float* __restrict__ w1,
    const float* __restrict__ w2, const float* __restrict__ w3,
    __nv_bfloat16* __restrict__ hi, __nv_bfloat16* __restrict__ lo)
{
    __shared__ float t[32][33];
    int z = blockIdx.z;
    const float* W = (z == 0) ? w0 : (z == 1) ? w1 : (z == 2) ? w2 : w3;
    __nv_bfloat16* H = hi + (size_t)z * DD * NCOLS;
    __nv_bfloat16* L = lo + (size_t)z * DD * NCOLS;
    int tx = threadIdx.x & 31, ty = threadIdx.x >> 5;
    int n0 = blockIdx.x * 32, k0 = blockIdx.y * 32;
#pragma unroll
    for (int i = 0; i < 4; i++)
        t[ty + i * 8][tx] = W[(size_t)(k0 + ty + i * 8) * NCOLS + n0 + tx];
    __syncthreads();
#pragma unroll
    for (int i = 0; i < 4; i++) {
        float v = t[tx][ty + i * 8];
        __nv_bfloat16 h, l;
        bf16_split(v, h, l);
        size_t o = (size_t)(n0 + ty + i * 8) * DD + k0 + tx;
        H[o] = h;
        L[o] = l;
    }
}

// ---------------- bf16x3 GEMM core: tile 128x64, warp 32x32 (unchanged) ----------------
#define BK2 32
#define BSTRW 24
#define ATILE_W (128*BSTRW)
#define BTILE_W (64*BSTRW)
#define GEMM_SMEM ((2*2*ATILE_W + 2*2*BTILE_W)*4)   // 73728 bytes
#define WSZ ((size_t)DD*NCOLS)

__device__ __forceinline__ void gemm_core(
    const __nv_bfloat16* __restrict__ Ahi, const __nv_bfloat16* __restrict__ Alo,
    const __nv_bfloat16* __restrict__ Bhi, const __nv_bfloat16* __restrict__ Blo,
    int Kdim, int bm, int bn, float c[2][4][4])
{
    extern __shared__ uint32_t smw[];
    uint32_t* sAH = smw;
    uint32_t* sAL = smw + 2 * ATILE_W;
    uint32_t* sBH = smw + 4 * ATILE_W;
    uint32_t* sBL = smw + 4 * ATILE_W + 2 * BTILE_W;
    const uint32_t uAH = smem_u32(sAH), uAL = smem_u32(sAL);
    const uint32_t uBH = smem_u32(sBH), uBL = smem_u32(sBL);

    const int tid = threadIdx.x, lane = tid & 31, wid = tid >> 5;
    const int grp = lane >> 2, qd = lane & 3;
    const int wm = (wid >> 1) << 5, wn = (wid & 1) << 5;

#pragma unroll
    for (int i = 0; i < 2; i++)
#pragma unroll
        for (int j = 0; j < 4; j++)
#pragma unroll
            for (int r = 0; r < 4; r++) c[i][j][r] = 0.0f;

    const int NKB = Kdim / BK2;

    auto load_stage = [&](int kb, int st) {
        int koff = kb * BK2;
#pragma unroll
        for (int i = 0; i < 2; i++) {
            int ch = i * 256 + tid;
            int row = ch >> 2, seg = ch & 3;
            size_t gA = (size_t)(bm + row) * Kdim + koff + seg * 8;
            uint32_t so = (st * ATILE_W + row * BSTRW + seg * 4) * 4;
            cp16(uAH + so, Ahi + gA);
            cp16(uAL + so, Alo + gA);
        }
        {
            int row = tid >> 2, seg = tid & 3;
            size_t gB = (size_t)(bn + row) * Kdim + koff + seg * 8;
            uint32_t so = (st * BTILE_W + row * BSTRW + seg * 4) * 4;
            cp16(uBH + so, Bhi + gB);
            cp16(uBL + so, Blo + gB);
        }
        cp_commit();
    };

    load_stage(0, 0);
    for (int kb = 0; kb < NKB; kb++) {
        int st = kb & 1;
        if (kb + 1 < NKB) { load_stage(kb + 1, st ^ 1); cp_wait<1>(); }
        else               { cp_wait<0>(); }
        __syncthreads();

        const uint32_t* AH = sAH + st * ATILE_W;
        const uint32_t* AL = sAL + st * ATILE_W;
        const uint32_t* BH = sBH + st * BTILE_W;
        const uint32_t* BL = sBL + st * BTILE_W;

#pragma unroll
        for (int ks = 0; ks < 2; ks++) {
            const int kw = ks * 8 + 2 * qd;
            uint32_t ah[2][4], bh[4][2];
#pragma unroll
            for (int mt = 0; mt < 2; mt++) {
                const uint32_t* p = AH + (wm + mt * 16 + grp) * BSTRW + kw;
                uint2 v0 = *(const uint2*)p;
                uint2 v1 = *(const uint2*)(p + 8 * BSTRW);
                ah[mt][0] = v0.x; ah[mt][2] = v0.y;
                ah[mt][1] = v1.x; ah[mt][3] = v1.y;
            }
#pragma unroll
            for (int nt = 0; nt < 4; nt++) {
                uint2 vb = *(const uint2*)(BH + (wn + nt * 8 + grp) * BSTRW + kw);
                bh[nt][0] = vb.x; bh[nt][1] = vb.y;
            }
#pragma unroll
            for (int mt = 0; mt < 2; mt++)
#pragma unroll
                for (int nt = 0; nt < 4; nt++) mma16(c[mt][nt], ah[mt], bh[nt]);

            {
                uint32_t bl[4][2];
#pragma unroll
                for (int nt = 0; nt < 4; nt++) {
                    uint2 vb = *(const uint2*)(BL + (wn + nt * 8 + grp) * BSTRW + kw);
                    bl[nt][0] = vb.x; bl[nt][1] = vb.y;
                }
#pragma unroll
                for (int mt = 0; mt < 2; mt++)
#pragma unroll
                    for (int nt = 0; nt < 4; nt++) mma16(c[mt][nt], ah[mt], bl[nt]);
            }
            {
                uint32_t al[2][4];
#pragma unroll
                for (int mt = 0; mt < 2; mt++) {
                    const uint32_t* p = AL + (wm + mt * 16 + grp) * BSTRW + kw;
                    uint2 v0 = *(const uint2*)p;
                    uint2 v1 = *(const uint2*)(p + 8 * BSTRW);
                    al[mt][0] = v0.x; al[mt][2] = v0.y;
                    al[mt][1] = v1.x; al[mt][3] = v1.y;
                }
#pragma unroll
                for (int mt = 0; mt < 2; mt++)
#pragma unroll
                    for (int nt = 0; nt < 4; nt++) mma16(c[mt][nt], al[mt], bh[nt]);
            }
        }
        __syncthreads();
    }
}

// merged Q/K/V projection: gridDim.z = 3
__global__ void __launch_bounds__(256, 2) gemm_qkv(
    const __nv_bfloat16* __restrict__ xhi, const __nv_bfloat16* __restrict__ xlo,
    const __nv_bfloat16* __restrict__ wthi, const __nv_bfloat16* __restrict__ wtlo,
    const float* __restrict__ bq, const float* __restrict__ bk, const float* __restrict__ bv,
    float* __restrict__ gq, float* __restrict__ gk,
    __half* __restrict__ vh, __half* __restrict__ vl)
{
    const int z = blockIdx.z;
    const int bm = blockIdx.y << 7, bn = blockIdx.x << 6;
    const float* bias = (z == 0) ? bq : (z == 1) ? bk : bv;
    const float scale = (z == 0) ? 0.125f : 1.0f;

    float c[2][4][4];
    gemm_core(xhi, xlo, wthi + (size_t)z * WSZ, wtlo + (size_t)z * WSZ, DD, bm, bn, c);

    const int lane = threadIdx.x & 31, wid = threadIdx.x >> 5;
    const int grp = lane >> 2, qd = lane & 3;
    const int wm = (wid >> 1) << 5, wn = (wid & 1) << 5;
    float* C = (z == 0) ? gq : gk;

#pragma unroll
    for (int mt = 0; mt < 2; mt++) {
#pragma unroll
        for (int nt = 0; nt < 4; nt++) {
            int n = bn + wn + nt * 8 + 2 * qd;
            float b0v = bias[n], b1v = bias[n + 1];
#pragma unroll
            for (int rr = 0; rr < 2; rr++) {
                int m = bm + wm + mt * 16 + grp + rr * 8;
                float v0 = (c[mt][nt][rr * 2 + 0] + b0v) * scale;
                float v1 = (c[mt][nt][rr * 2 + 1] + b1v) * scale;
                int b_ = m >> 11, s = m & 2047;
                int h = n >> 6, hd = n & 63;
                if (z < 2) {
                    float2 o = make_float2(tf32_rna(v0), tf32_rna(v1));
                    *(float2*)&C[((size_t)(b_ * HH + h) * SS + s) * HDD + hd] = o;
                } else {
                    // key-word interleave within each 16-key group:
                    // logical word w -> physical word (w<4 ? 2w : 2w-7)
                    int k16 = s & 15, gb = s & ~15;
                    int w = k16 >> 1, e = k16 & 1;
                    int pw = (w < 4) ? (2 * w) : (2 * w - 7);
                    int sp = gb + 2 * pw + e;
                    size_t off = ((size_t)((b_ * HH + h) * HDD + hd)) * SS + sp;
                    __half hh0, ll0, hh1, ll1;
                    f16_split(v0, hh0, ll0);
                    f16_split(v1, hh1, ll1);
                    vh[off] = hh0;       vl[off] = ll0;
                    vh[off + SS] = hh1;  vl[off + SS] = ll1;
                }
            }
        }
    }
}

// O projection: plain row-major f32 output
__global__ void __launch_bounds__(256, 2) gemm_o(
    const __nv_bfloat16* __restrict__ ohi, const __nv_bfloat16* __restrict__ olo,
    const __nv_bfloat16* __restrict__ wthi, const __nv_bfloat16* __restrict__ wtlo,
    const float* __restrict__ bias, float* __restrict__ C)
{
    const int bm = blockIdx.y << 7, bn = blockIdx.x << 6;
    float c[2][4][4];
    gemm_core(ohi, olo, wthi, wtlo, NCOLS, bm, bn, c);

    const int lane = threadIdx.x & 31, wid = threadIdx.x >> 5;
    const int grp = lane >> 2, qd = lane & 3;
    const int wm = (wid >> 1) << 5, wn = (wid & 1) << 5;
#pragma unroll
    for (int mt = 0; mt < 2; mt++) {
#pragma unroll
        for (int nt = 0; nt < 4; nt++) {
            int n = bn + wn + nt * 8 + 2 * qd;
            float b0v = bias[n], b1v = bias[n + 1];
#pragma unroll
            for (int rr = 0; rr < 2; rr++) {
                int m = bm + wm + mt * 16 + grp + rr * 8;
                float v0 = c[mt][nt][rr * 2 + 0] + b0v;
                float v1 = c[mt][nt][rr * 2 + 1] + b1v;
                *(float2*)&C[(size_t)m * NCOLS + n] = make_float2(v0, v1);
            }
        }
    }
}

// ---------------- flash attention v4: QK tf32, PV fp16 (P single, V hi/lo) ----------------
// V^T fp16, key-word interleaved so each thread's B-fragment pair is one LDS.64.
// VSTW=40: bank-pair (20*grp + qd) % 16 distinct per phase -> conflict-free.
#define QSTR 72
#define KSTR 72
#define VSTW 40
#define QOFF 0                            // 9216 f32 words
#define KOFF  (128*QSTR)                  // 9216
#define VHOFF (KOFF + 64*KSTR)            // u32 words: 2 stages x 64 x 40 = 5120
#define VLOFF (VHOFF + 2*64*VSTW)
#define FLASH_WORDS (VLOFF + 2*64*VSTW)   // 28672
#define FLASH_SMEM (FLASH_WORDS*4)        // 114688 B -> 2 CTAs/SM

__global__ void __launch_bounds__(256, 2) flash_kernel(
    const float* __restrict__ gq, const float* __restrict__ gk,
    const __half* __restrict__ gvh, const __half* __restrict__ gvl,
    float* __restrict__ go)
{
    extern __shared__ float smf[];
    uint32_t* smw = (uint32_t*)smf;
    const uint32_t sb = smem_u32(smf);

    const int tid = threadIdx.x, lane = tid & 31, wid = tid >> 5;
    const int grp = lane >> 2, qd = lane & 3;
    const int qt = blockIdx.x;
    const int bh = blockIdx.y;

    const float* Qg = gq  + ((size_t)bh * SS + qt * 128) * HDD;
    const float* Kg = gk  + (size_t)bh * SS * HDD;
    const __half* Vh = gvh + (size_t)bh * HDD * SS;
    const __half* Vl = gvl + (size_t)bh * HDD * SS;

    auto load_kv = [&](int kt, int st) {
#pragma unroll
        for (int i = 0; i < 4; i++) {
            int ch = i * 256 + tid;
            int row = ch >> 4, seg = ch & 15;
            cp16(sb + (KOFF + row * KSTR) * 4 + seg * 16,
                 Kg + (size_t)(kt * 64 + row) * 64 + seg * 4);
        }
#pragma unroll
        for (int i = 0; i < 2; i++) {
            int ch = i * 256 + tid;
            int row = ch >> 3, seg = ch & 7;
            size_t g = (size_t)row * SS + kt * 64 + seg * 8;
            cp16(sb + (VHOFF + st * 64 * VSTW + row * VSTW + seg * 4) * 4, Vh + g);
            cp16(sb + (VLOFF + st * 64 * VSTW + row * VSTW + seg * 4) * 4, Vl + g);
        }
        cp_commit();
    };

    // prologue: Q + first K/V
#pragma unroll
    for (int i = 0; i < 8; i++) {
        int ch = i * 256 + tid;
        int row = ch >> 4, seg = ch & 15;
        cp16(sb + (QOFF + row * QSTR) * 4 + seg * 16, Qg + row * 64 + seg * 4);
    }
    load_kv(0, 0);

    float co[8][4];
#pragma unroll
    for (int i = 0; i < 8; i++)
#pragma unroll
        for (int r = 0; r < 4; r++) co[i][r] = 0.0f;
    float m0 = -1e30f, m1 = -1e30f, l0 = 0.0f, l1 = 0.0f;

    const int r0 = wid * 16;
    const float* Qrow = smf + QOFF + (r0 + grp) * QSTR;
    const float* Kb = smf + KOFF;

    for (int kt = 0; kt < SS / 64; kt++) {
        const int st = kt & 1;
        cp_wait<0>();
        __syncthreads();                // K[kt] + V[kt] resident; prior reads done

        // ---- S = Q K^T (tf32; logical-d remap, LDS.64 operands)
        float cs[8][4];
#pragma unroll
        for (int i = 0; i < 8; i++)
#pragma unroll
            for (int r = 0; r < 4; r++) cs[i][r] = 0.0f;
#pragma unroll
        for (int ks = 0; ks < 8; ks++) {
            const int d = ks * 8 + 2 * qd;
            uint32_t a[4];
            uint2 qa0 = *(const uint2*)(Qrow + d);
            uint2 qa1 = *(const uint2*)(Qrow + 8 * QSTR + d);
            a[0] = qa0.x; a[2] = qa0.y;
            a[1] = qa1.x; a[3] = qa1.y;
#pragma unroll
            for (int nt = 0; nt < 8; nt++) {
                uint2 bb = *(const uint2*)(Kb + (nt * 8 + grp) * KSTR + d);
                uint32_t b[2];
                b[0] = bb.x; b[1] = bb.y;
                mma8(cs[nt], a, b);
            }
        }

        __syncthreads();                // all warps done reading K[kt]
        if (kt + 1 < SS / 64) load_kv(kt + 1, st ^ 1);

        // ---- online softmax: row max
        float mx0 = -1e30f, mx1 = -1e30f;
#pragma unroll
        for (int nt = 0; nt < 8; nt++) {
            mx0 = fmaxf(mx0, fmaxf(cs[nt][0], cs[nt][1]));
            mx1 = fmaxf(mx1, fmaxf(cs[nt][2], cs[nt][3]));
        }
        mx0 = fmaxf(mx0, __shfl_xor_sync(0xffffffffu, mx0, 1));
        mx0 = fmaxf(mx0, __shfl_xor_sync(0xffffffffu, mx0, 2));
        mx1 = fmaxf(mx1, __shfl_xor_sync(0xffffffffu, mx1, 1));
        mx1 = fmaxf(mx1, __shfl_xor_sync(0xffffffffu, mx1, 2));
        float mn0 = fmaxf(m0, mx0), mn1 = fmaxf(m1, mx1);
        float al0 = __expf(m0 - mn0), al1 = __expf(m1 - mn1);
        m0 = mn0;
        m1 = mn1;
#pragma unroll
        for (int nt = 0; nt < 8; nt++) {
            co[nt][0] *= al0; co[nt][1] *= al0;
            co[nt][2] *= al1; co[nt][3] *= al1;
        }

        const uint32_t* VhB = smw + VHOFF + st * 64 * VSTW;
        const uint32_t* VlB = smw + VLOFF + st * 64 * VSTW;
        float s0 = 0.0f, s1 = 0.0f;

        // ---- fused exp + PV: P fragments (fp16) in registers, V hi/lo LDS.64
#pragma unroll
        for (int ks2 = 0; ks2 < 4; ks2++) {
            const int t0 = 2 * ks2, t1 = t0 + 1;
            float p00 = __expf(cs[t0][0] - mn0);
            float p01 = __expf(cs[t0][1] - mn0);
            float p02 = __expf(cs[t0][2] - mn1);
            float p03 = __expf(cs[t0][3] - mn1);
            float p10 = __expf(cs[t1][0] - mn0);
            float p11 = __expf(cs[t1][1] - mn0);
            float p12 = __expf(cs[t1][2] - mn1);
            float p13 = __expf(cs[t1][3] - mn1);
            s0 += (p00 + p01) + (p10 + p11);
            s1 += (p02 + p03) + (p12 + p13);

            uint32_t aP[4];
            aP[0] = pack_f16(p00, p01);
            aP[1] = pack_f16(p02, p03);
            aP[2] = pack_f16(p10, p11);
            aP[3] = pack_f16(p12, p13);

            const int w0 = ks2 * 8 + 2 * qd;   // interleaved: words (qd, qd+4) adjacent
#pragma unroll
            for (int nt = 0; nt < 8; nt++) {
                uint2 vb = *(const uint2*)(VhB + (nt * 8 + grp) * VSTW + w0);
                uint32_t b[2];
                b[0] = vb.x; b[1] = vb.y;
                mma16h(co[nt], aP, b);
                uint2 vl2 = *(const uint2*)(VlB + (nt * 8 + grp) * VSTW + w0);
                b[0] = vl2.x; b[1] = vl2.y;
                mma16h(co[nt], aP, b);
            }
        }

        s0 += __shfl_xor_sync(0xffffffffu, s0, 1);
        s0 += __shfl_xor_sync(0xffffffffu, s0, 2);
        s1 += __shfl_xor_sync(0xffffffffu, s1, 1);
        s1 += __shfl_xor_sync(0xffffffffu, s1, 2);
        l0 = l0 * al0 + s0;
        l1 = l1 * al1 + s1;
    }

    const int b_ = bh >> 4;
    const int h  = bh & 15;
    const float inv0 = 1.0f / l0, inv1 = 1.0f / l1;
    const int q0 = qt * 128 + r0 + grp;
#pragma unroll
    for (int nt = 0; nt < 8; nt++) {
        int n = nt * 8 + 2 * qd;
        *(float2*)&go[((size_t)(b_ * SS + q0) * HH + h) * HDD + n] =
            make_float2(co[nt][0] * inv0, co[nt][1] * inv0);
        *(float2*)&go[((size_t)(b_ * SS + q0 + 8) * HH + h) * HDD + n] =
            make_float2(co[nt][2] * inv1, co[nt][3] * inv1);
    }
}

// ---------------------------------------------------------------------------
extern "C" void kernel_launch(void* const* d_in, const int* in_sizes, int n_in,
                              void* d_out, int out_size)
{
    const float* x  = (const float*)d_in[0];
    const float* wq = (const float*)d_in[1];
    const float* bq = (const float*)d_in[2];
    const float* wk = (const float*)d_in[3];
    const float* bk = (const float*)d_in[4];
    const float* wv = (const float*)d_in[5];
    const float* bv = (const float*)d_in[6];
    const float* wo = (const float*)d_in[7];
    const float* bo = (const float*)d_in[8];
    float* out = (float*)d_out;

    float *gq, *gk, *go;
    __half *gvh, *gvl;
    __nv_bfloat16 *xhi, *xlo, *ohi, *olo, *wthi, *wtlo;
    cudaGetSymbolAddress((void**)&gq,   g_q);
    cudaGetSymbolAddress((void**)&gk,   g_k);
    cudaGetSymbolAddress((void**)&gvh,  g_vhi);
    cudaGetSymbolAddress((void**)&gvl,  g_vlo);
    cudaGetSymbolAddress((void**)&go,   g_o);
    cudaGetSymbolAddress((void**)&xhi,  g_xhi);
    cudaGetSymbolAddress((void**)&xlo,  g_xlo);
    cudaGetSymbolAddress((void**)&ohi,  g_ohi);
    cudaGetSymbolAddress((void**)&olo,  g_olo);
    cudaGetSymbolAddress((void**)&wthi, g_wthi);
    cudaGetSymbolAddress((void**)&wtlo, g_wtlo);

    cudaFuncSetAttribute(gemm_qkv, cudaFuncAttributeMaxDynamicSharedMemorySize, GEMM_SMEM);
    cudaFuncSetAttribute(gemm_o,   cudaFuncAttributeMaxDynamicSharedMemorySize, GEMM_SMEM);
    cudaFuncSetAttribute(flash_kernel, cudaFuncAttributeMaxDynamicSharedMemorySize, FLASH_SMEM);

    // prep
    split_kernel<<<(MROWS * DD / 4 + 255) / 256, 256>>>(x, xhi, xlo, MROWS * DD / 4);
    transpose_split_kernel<<<dim3(NCOLS / 32, DD / 32, 4), 256>>>(wq, wk, wv, wo, wthi, wtlo);

    gemm_qkv<<<dim3(NCOLS / 64, MROWS / 128, 3), 256, GEMM_SMEM>>>(
        xhi, xlo, wthi, wtlo, bq, bk, bv, gq, gk, gvh, gvl);

    flash_kernel<<<dim3(SS / 128, BB * HH), 256, FLASH_SMEM>>>(gq, gk, gvh, gvl, go);

    split_kernel<<<(MROWS * NCOLS / 4 + 255) / 256, 256>>>(go, ohi, olo, MROWS * NCOLS / 4);
    gemm_o<<<dim3(NCOLS / 64, MROWS / 128), 256, GEMM_SMEM>>>(
        ohi, olo, wthi + 3 * WSZ, wtlo + 3 * WSZ, bo, out);
}

// round 15
// speedup vs baseline: 1.5576x; 1.0471x over previous
#include <cuda_runtime.h>
#include <cuda_bf16.h>
#include <cuda_fp16.h>
#include <cstdint>

#define BB 2
#define SS 2048
#define DD 1024
#define HH 16
#define HDD 64
#define MROWS (BB*SS)    // 4096
#define NCOLS (HH*HDD)   // 1024

// ---------------- scratch (__device__ globals; allocation-free rule) ----------------
__device__ float g_q  [(size_t)MROWS*NCOLS];  // [B,H,S,HD], tf32-rounded, pre-scaled 1/8
__device__ float g_k  [(size_t)MROWS*NCOLS];  // [B,H,S,HD], tf32-rounded
__device__ __half g_vhi[(size_t)MROWS*NCOLS]; // V^T [B,H,HD,S] fp16 hi (key-word interleaved)
__device__ __half g_vlo[(size_t)MROWS*NCOLS]; // V^T fp16 lo
__device__ float g_o  [(size_t)MROWS*NCOLS];  // [B,S,H*HD] attention out
__device__ __nv_bfloat16 g_xhi[(size_t)MROWS*DD];    // x split, bf16
__device__ __nv_bfloat16 g_xlo[(size_t)MROWS*DD];
__device__ __nv_bfloat16 g_ohi[(size_t)MROWS*NCOLS]; // attn-out split, bf16
__device__ __nv_bfloat16 g_olo[(size_t)MROWS*NCOLS];
__device__ __nv_bfloat16 g_wthi[(size_t)4*DD*NCOLS]; // 4 transposed weights [N,K], bf16 hi
__device__ __nv_bfloat16 g_wtlo[(size_t)4*DD*NCOLS]; // lo

// ---------------- helpers ----------------
__device__ __forceinline__ uint32_t smem_u32(const void* p) {
    uint32_t a;
    asm("{ .reg .u64 t; cvta.to.shared.u64 t, %1; cvt.u32.u64 %0, t; }" : "=r"(a) : "l"(p));
    return a;
}
__device__ __forceinline__ float tf32_rna(float v) {
    uint32_t r;
    asm("cvt.rna.tf32.f32 %0, %1;" : "=r"(r) : "f"(v));
    return __uint_as_float(r);
}
__device__ __forceinline__ uint32_t f2b(float v) { return __float_as_uint(v); }
// pack two f32 -> f16x2 word, first arg in bits[15:0]
__device__ __forceinline__ uint32_t pack_f16(float lo, float hi) {
    uint32_t r;
    asm("cvt.rn.f16x2.f32 %0, %1, %2;" : "=r"(r) : "f"(hi), "f"(lo));
    return r;
}

__device__ __forceinline__ void cp16(uint32_t s, const void* g) {
    asm volatile("cp.async.cg.shared.global [%0], [%1], 16;" :: "r"(s), "l"(g));
}
__device__ __forceinline__ void cp_commit() { asm volatile("cp.async.commit_group;"); }
template<int N>
__device__ __forceinline__ void cp_wait() {
    asm volatile("cp.async.wait_group %0;" :: "n"(N) : "memory");
}

// mma.sync m16n8k8 tf32 (flash QK)
__device__ __forceinline__ void mma8(float* c, const uint32_t* a, const uint32_t* b) {
    asm volatile(
        "mma.sync.aligned.m16n8k8.row.col.f32.tf32.tf32.f32 "
        "{%0,%1,%2,%3}, {%4,%5,%6,%7}, {%8,%9}, {%0,%1,%2,%3};"
        : "+f"(c[0]), "+f"(c[1]), "+f"(c[2]), "+f"(c[3])
        : "r"(a[0]), "r"(a[1]), "r"(a[2]), "r"(a[3]), "r"(b[0]), "r"(b[1]));
}
// mma.sync m16n8k16 bf16 (GEMMs)
__device__ __forceinline__ void mma16(float* c, const uint32_t* a, const uint32_t* b) {
    asm volatile(
        "mma.sync.aligned.m16n8k16.row.col.f32.bf16.bf16.f32 "
        "{%0,%1,%2,%3}, {%4,%5,%6,%7}, {%8,%9}, {%0,%1,%2,%3};"
        : "+f"(c[0]), "+f"(c[1]), "+f"(c[2]), "+f"(c[3])
        : "r"(a[0]), "r"(a[1]), "r"(a[2]), "r"(a[3]), "r"(b[0]), "r"(b[1]));
}
// mma.sync m16n8k16 fp16 (flash PV)
__device__ __forceinline__ void mma16h(float* c, const uint32_t* a, const uint32_t* b) {
    asm volatile(
        "mma.sync.aligned.m16n8k16.row.col.f32.f16.f16.f32 "
        "{%0,%1,%2,%3}, {%4,%5,%6,%7}, {%8,%9}, {%0,%1,%2,%3};"
        : "+f"(c[0]), "+f"(c[1]), "+f"(c[2]), "+f"(c[3])
        : "r"(a[0]), "r"(a[1]), "r"(a[2]), "r"(a[3]), "r"(b[0]), "r"(b[1]));
}

__device__ __forceinline__ void bf16_split(float v, __nv_bfloat16& h, __nv_bfloat16& l) {
    h = __float2bfloat16(v);
    l = __float2bfloat16(v - __bfloat162float(h));
}
__device__ __forceinline__ void f16_split(float v, __half& h, __half& l) {
    h = __float2half_rn(v);
    l = __float2half_rn(v - __half2float(h));
}

// ---------------- prep kernels ----------------
struct alignas(8) bf16x4 { __nv_bfloat162 a, b; };

__global__ void __launch_bounds__(256) split_kernel(const float* __restrict__ in,
                                                    __nv_bfloat16* __restrict__ hi,
                                                    __nv_bfloat16* __restrict__ lo, int n4) {
    int i = blockIdx.x * blockDim.x + threadIdx.x;
    if (i < n4) {
        float4 v = ((const float4*)in)[i];
        __nv_bfloat16 h0, h1, h2, h3, l0, l1, l2, l3;
        bf16_split(v.x, h0, l0);
        bf16_split(v.y, h1, l1);
        bf16_split(v.z, h2, l2);
        bf16_split(v.w, h3, l3);
        bf16x4 H; H.a = __nv_bfloat162(h0, h1); H.b = __nv_bfloat162(h2, h3);
        bf16x4 L; L.a = __nv_bfloat162(l0, l1); L.b = __nv_bfloat162(l2, l3);
        ((bf16x4*)hi)[i] = H;
        ((bf16x4*)lo)[i] = L;
    }
}

// W [K=1024][N=1024] -> Wt hi/lo [N][K] bf16, 4 matrices via blockIdx.z
__global__ void __launch_bounds__(256) transpose_split_kernel(
    const float* __restrict__ w0, const float* __restrict__ w1,
    const float* __restrict__ w2, const float* __restrict__ w3,
    __nv_bfloat16* __restrict__ hi, __nv_bfloat16* __restrict__ lo)
{
    __shared__ float t[32][33];
    int z = blockIdx.z;
    const float* W = (z == 0) ? w0 : (z == 1) ? w1 : (z == 2) ? w2 : w3;
    __nv_bfloat16* H = hi + (size_t)z * DD * NCOLS;
    __nv_bfloat16* L = lo + (size_t)z * DD * NCOLS;
    int tx = threadIdx.x & 31, ty = threadIdx.x >> 5;
    int n0 = blockIdx.x * 32, k0 = blockIdx.y * 32;
#pragma unroll
    for (int i = 0; i < 4; i++)
        t[ty + i * 8][tx] = W[(size_t)(k0 + ty + i * 8) * NCOLS + n0 + tx];
    __syncthreads();
#pragma unroll
    for (int i = 0; i < 4; i++) {
        float v = t[tx][ty + i * 8];
        __nv_bfloat16 h, l;
        bf16_split(v, h, l);
        size_t o = (size_t)(n0 + ty + i * 8) * DD + k0 + tx;
        H[o] = h;
        L[o] = l;
    }
}

// ---------------- bf16x3 GEMM core: tile 128x64, warp 32x32 (unchanged) ----------------
#define BK2 32
#define BSTRW 24
#define ATILE_W (128*BSTRW)
#define BTILE_W (64*BSTRW)
#define GEMM_SMEM ((2*2*ATILE_W + 2*2*BTILE_W)*4)   // 73728 bytes
#define WSZ ((size_t)DD*NCOLS)

__device__ __forceinline__ void gemm_core(
    const __nv_bfloat16* __restrict__ Ahi, const __nv_bfloat16* __restrict__ Alo,
    const __nv_bfloat16* __restrict__ Bhi, const __nv_bfloat16* __restrict__ Blo,
    int Kdim, int bm, int bn, float c[2][4][4])
{
    extern __shared__ uint32_t smw[];
    uint32_t* sAH = smw;
    uint32_t* sAL = smw + 2 * ATILE_W;
    uint32_t* sBH = smw + 4 * ATILE_W;
    uint32_t* sBL = smw + 4 * ATILE_W + 2 * BTILE_W;
    const uint32_t uAH = smem_u32(sAH), uAL = smem_u32(sAL);
    const uint32_t uBH = smem_u32(sBH), uBL = smem_u32(sBL);

    const int tid = threadIdx.x, lane = tid & 31, wid = tid >> 5;
    const int grp = lane >> 2, qd = lane & 3;
    const int wm = (wid >> 1) << 5, wn = (wid & 1) << 5;

#pragma unroll
    for (int i = 0; i < 2; i++)
#pragma unroll
        for (int j = 0; j < 4; j++)
#pragma unroll
            for (int r = 0; r < 4; r++) c[i][j][r] = 0.0f;

    const int NKB = Kdim / BK2;

    auto load_stage = [&](int kb, int st) {
        int koff = kb * BK2;
#pragma unroll
        for (int i = 0; i < 2; i++) {
            int ch = i * 256 + tid;
            int row = ch >> 2, seg = ch & 3;
            size_t gA = (size_t)(bm + row) * Kdim + koff + seg * 8;
            uint32_t so = (st * ATILE_W + row * BSTRW + seg * 4) * 4;
            cp16(uAH + so, Ahi + gA);
            cp16(uAL + so, Alo + gA);
        }
        {
            int row = tid >> 2, seg = tid & 3;
            size_t gB = (size_t)(bn + row) * Kdim + koff + seg * 8;
            uint32_t so = (st * BTILE_W + row * BSTRW + seg * 4) * 4;
            cp16(uBH + so, Bhi + gB);
            cp16(uBL + so, Blo + gB);
        }
        cp_commit();
    };

    load_stage(0, 0);
    for (int kb = 0; kb < NKB; kb++) {
        int st = kb & 1;
        if (kb + 1 < NKB) { load_stage(kb + 1, st ^ 1); cp_wait<1>(); }
        else               { cp_wait<0>(); }
        __syncthreads();

        const uint32_t* AH = sAH + st * ATILE_W;
        const uint32_t* AL = sAL + st * ATILE_W;
        const uint32_t* BH = sBH + st * BTILE_W;
        const uint32_t* BL = sBL + st * BTILE_W;

#pragma unroll
        for (int ks = 0; ks < 2; ks++) {
            const int kw = ks * 8 + 2 * qd;
            uint32_t ah[2][4], bh[4][2];
#pragma unroll
            for (int mt = 0; mt < 2; mt++) {
                const uint32_t* p = AH + (wm + mt * 16 + grp) * BSTRW + kw;
                uint2 v0 = *(const uint2*)p;
                uint2 v1 = *(const uint2*)(p + 8 * BSTRW);
                ah[mt][0] = v0.x; ah[mt][2] = v0.y;
                ah[mt][1] = v1.x; ah[mt][3] = v1.y;
            }
#pragma unroll
            for (int nt = 0; nt < 4; nt++) {
                uint2 vb = *(const uint2*)(BH + (wn + nt * 8 + grp) * BSTRW + kw);
                bh[nt][0] = vb.x; bh[nt][1] = vb.y;
            }
#pragma unroll
            for (int mt = 0; mt < 2; mt++)
#pragma unroll
                for (int nt = 0; nt < 4; nt++) mma16(c[mt][nt], ah[mt], bh[nt]);

            {
                uint32_t bl[4][2];
#pragma unroll
                for (int nt = 0; nt < 4; nt++) {
                    uint2 vb = *(const uint2*)(BL + (wn + nt * 8 + grp) * BSTRW + kw);
                    bl[nt][0] = vb.x; bl[nt][1] = vb.y;
                }
#pragma unroll
                for (int mt = 0; mt < 2; mt++)
#pragma unroll
                    for (int nt = 0; nt < 4; nt++) mma16(c[mt][nt], ah[mt], bl[nt]);
            }
            {
                uint32_t al[2][4];
#pragma unroll
                for (int mt = 0; mt < 2; mt++) {
                    const uint32_t* p = AL + (wm + mt * 16 + grp) * BSTRW + kw;
                    uint2 v0 = *(const uint2*)p;
                    uint2 v1 = *(const uint2*)(p + 8 * BSTRW);
                    al[mt][0] = v0.x; al[mt][2] = v0.y;
                    al[mt][1] = v1.x; al[mt][3] = v1.y;
                }
#pragma unroll
                for (int mt = 0; mt < 2; mt++)
#pragma unroll
                    for (int nt = 0; nt < 4; nt++) mma16(c[mt][nt], al[mt], bh[nt]);
            }
        }
        __syncthreads();
    }
}

// merged Q/K/V projection: gridDim.z = 3
__global__ void __launch_bounds__(256, 2) gemm_qkv(
    const __nv_bfloat16* __restrict__ xhi, const __nv_bfloat16* __restrict__ xlo,
    const __nv_bfloat16* __restrict__ wthi, const __nv_bfloat16* __restrict__ wtlo,
    const float* __restrict__ bq, const float* __restrict__ bk, const float* __restrict__ bv,
    float* __restrict__ gq, float* __restrict__ gk,
    __half* __restrict__ vh, __half* __restrict__ vl)
{
    const int z = blockIdx.z;
    const int bm = blockIdx.y << 7, bn = blockIdx.x << 6;
    const float* bias = (z == 0) ? bq : (z == 1) ? bk : bv;
    const float scale = (z == 0) ? 0.125f : 1.0f;

    float c[2][4][4];
    gemm_core(xhi, xlo, wthi + (size_t)z * WSZ, wtlo + (size_t)z * WSZ, DD, bm, bn, c);

    const int lane = threadIdx.x & 31, wid = threadIdx.x >> 5;
    const int grp = lane >> 2, qd = lane & 3;
    const int wm = (wid >> 1) << 5, wn = (wid & 1) << 5;
    float* C = (z == 0) ? gq : gk;

#pragma unroll
    for (int mt = 0; mt < 2; mt++) {
#pragma unroll
        for (int nt = 0; nt < 4; nt++) {
            int n = bn + wn + nt * 8 + 2 * qd;
            float b0v = bias[n], b1v = bias[n + 1];
#pragma unroll
            for (int rr = 0; rr < 2; rr++) {
                int m = bm + wm + mt * 16 + grp + rr * 8;
                float v0 = (c[mt][nt][rr * 2 + 0] + b0v) * scale;
                float v1 = (c[mt][nt][rr * 2 + 1] + b1v) * scale;
                int b_ = m >> 11, s = m & 2047;
                int h = n >> 6, hd = n & 63;
                if (z < 2) {
                    float2 o = make_float2(tf32_rna(v0), tf32_rna(v1));
                    *(float2*)&C[((size_t)(b_ * HH + h) * SS + s) * HDD + hd] = o;
                } else {
                    // key-word interleave within each 16-key group:
                    // logical word w -> physical word (w<4 ? 2w : 2w-7)
                    int k16 = s & 15, gb = s & ~15;
                    int w = k16 >> 1, e = k16 & 1;
                    int pw = (w < 4) ? (2 * w) : (2 * w - 7);
                    int sp = gb + 2 * pw + e;
                    size_t off = ((size_t)((b_ * HH + h) * HDD + hd)) * SS + sp;
                    __half hh0, ll0, hh1, ll1;
                    f16_split(v0, hh0, ll0);
                    f16_split(v1, hh1, ll1);
                    vh[off] = hh0;       vl[off] = ll0;
                    vh[off + SS] = hh1;  vl[off + SS] = ll1;
                }
            }
        }
    }
}

// O projection: plain row-major f32 output
__global__ void __launch_bounds__(256, 2) gemm_o(
    const __nv_bfloat16* __restrict__ ohi, const __nv_bfloat16* __restrict__ olo,
    const __nv_bfloat16* __restrict__ wthi, const __nv_bfloat16* __restrict__ wtlo,
    const float* __restrict__ bias, float* __restrict__ C)
{
    const int bm = blockIdx.y << 7, bn = blockIdx.x << 6;
    float c[2][4][4];
    gemm_core(ohi, olo, wthi, wtlo, NCOLS, bm, bn, c);

    const int lane = threadIdx.x & 31, wid = threadIdx.x >> 5;
    const int grp = lane >> 2, qd = lane & 3;
    const int wm = (wid >> 1) << 5, wn = (wid & 1) << 5;
#pragma unroll
    for (int mt = 0; mt < 2; mt++) {
#pragma unroll
        for (int nt = 0; nt < 4; nt++) {
            int n = bn + wn + nt * 8 + 2 * qd;
            float b0v = bias[n], b1v = bias[n + 1];
#pragma unroll
            for (int rr = 0; rr < 2; rr++) {
                int m = bm + wm + mt * 16 + grp + rr * 8;
                float v0 = c[mt][nt][rr * 2 + 0] + b0v;
                float v1 = c[mt][nt][rr * 2 + 1] + b1v;
                *(float2*)&C[(size_t)m * NCOLS + n] = make_float2(v0, v1);
            }
        }
    }
}

// ---------------- flash attention v4: QK tf32, PV fp16 (P single, V hi/lo) ----------------
// V^T fp16, key-word interleaved so each thread's B-fragment pair is one LDS.64.
// VSTW=40: bank-pair (20*grp + qd) % 16 distinct per phase -> conflict-free.
#define QSTR 72
#define KSTR 72
#define VSTW 40
#define QOFF 0                            // 9216 f32 words
#define KOFF  (128*QSTR)                  // 9216
#define VHOFF (KOFF + 64*KSTR)            // u32 words: 2 stages x 64 x 40 = 5120
#define VLOFF (VHOFF + 2*64*VSTW)
#define FLASH_WORDS (VLOFF + 2*64*VSTW)   // 28672
#define FLASH_SMEM (FLASH_WORDS*4)        // 114688 B -> 2 CTAs/SM

__global__ void __launch_bounds__(256, 2) flash_kernel(
    const float* __restrict__ gq, const float* __restrict__ gk,
    const __half* __restrict__ gvh, const __half* __restrict__ gvl,
    float* __restrict__ go)
{
    extern __shared__ float smf[];
    uint32_t* smw = (uint32_t*)smf;
    const uint32_t sb = smem_u32(smf);

    const int tid = threadIdx.x, lane = tid & 31, wid = tid >> 5;
    const int grp = lane >> 2, qd = lane & 3;
    const int qt = blockIdx.x;
    const int bh = blockIdx.y;

    const float* Qg = gq  + ((size_t)bh * SS + qt * 128) * HDD;
    const float* Kg = gk  + (size_t)bh * SS * HDD;
    const __half* Vh = gvh + (size_t)bh * HDD * SS;
    const __half* Vl = gvl + (size_t)bh * HDD * SS;

    auto load_kv = [&](int kt, int st) {
#pragma unroll
        for (int i = 0; i < 4; i++) {
            int ch = i * 256 + tid;
            int row = ch >> 4, seg = ch & 15;
            cp16(sb + (KOFF + row * KSTR) * 4 + seg * 16,
                 Kg + (size_t)(kt * 64 + row) * 64 + seg * 4);
        }
#pragma unroll
        for (int i = 0; i < 2; i++) {
            int ch = i * 256 + tid;
            int row = ch >> 3, seg = ch & 7;
            size_t g = (size_t)row * SS + kt * 64 + seg * 8;
            cp16(sb + (VHOFF + st * 64 * VSTW + row * VSTW + seg * 4) * 4, Vh + g);
            cp16(sb + (VLOFF + st * 64 * VSTW + row * VSTW + seg * 4) * 4, Vl + g);
        }
        cp_commit();
    };

    // prologue: Q + first K/V
#pragma unroll
    for (int i = 0; i < 8; i++) {
        int ch = i * 256 + tid;
        int row = ch >> 4, seg = ch & 15;
        cp16(sb + (QOFF + row * QSTR) * 4 + seg * 16, Qg + row * 64 + seg * 4);
    }
    load_kv(0, 0);

    float co[8][4];
#pragma unroll
    for (int i = 0; i < 8; i++)
#pragma unroll
        for (int r = 0; r < 4; r++) co[i][r] = 0.0f;
    float m0 = -1e30f, m1 = -1e30f, l0 = 0.0f, l1 = 0.0f;

    const int r0 = wid * 16;
    const float* Qrow = smf + QOFF + (r0 + grp) * QSTR;
    const float* Kb = smf + KOFF;

    for (int kt = 0; kt < SS / 64; kt++) {
        const int st = kt & 1;
        cp_wait<0>();
        __syncthreads();                // K[kt] + V[kt] resident; prior reads done

        // ---- S = Q K^T (tf32; logical-d remap, LDS.64 operands)
        float cs[8][4];
#pragma unroll
        for (int i = 0; i < 8; i++)
#pragma unroll
            for (int r = 0; r < 4; r++) cs[i][r] = 0.0f;
#pragma unroll
        for (int ks = 0; ks < 8; ks++) {
            const int d = ks * 8 + 2 * qd;
            uint32_t a[4];
            uint2 qa0 = *(const uint2*)(Qrow + d);
            uint2 qa1 = *(const uint2*)(Qrow + 8 * QSTR + d);
            a[0] = qa0.x; a[2] = qa0.y;
            a[1] = qa1.x; a[3] = qa1.y;
#pragma unroll
            for (int nt = 0; nt < 8; nt++) {
                uint2 bb = *(const uint2*)(Kb + (nt * 8 + grp) * KSTR + d);
                uint32_t b[2];
                b[0] = bb.x; b[1] = bb.y;
                mma8(cs[nt], a, b);
            }
        }

        __syncthreads();                // all warps done reading K[kt]
        if (kt + 1 < SS / 64) load_kv(kt + 1, st ^ 1);

        // ---- online softmax: row max
        float mx0 = -1e30f, mx1 = -1e30f;
#pragma unroll
        for (int nt = 0; nt < 8; nt++) {
            mx0 = fmaxf(mx0, fmaxf(cs[nt][0], cs[nt][1]));
            mx1 = fmaxf(mx1, fmaxf(cs[nt][2], cs[nt][3]));
        }
        mx0 = fmaxf(mx0, __shfl_xor_sync(0xffffffffu, mx0, 1));
        mx0 = fmaxf(mx0, __shfl_xor_sync(0xffffffffu, mx0, 2));
        mx1 = fmaxf(mx1, __shfl_xor_sync(0xffffffffu, mx1, 1));
        mx1 = fmaxf(mx1, __shfl_xor_sync(0xffffffffu, mx1, 2));
        float mn0 = fmaxf(m0, mx0), mn1 = fmaxf(m1, mx1);
        float al0 = __expf(m0 - mn0), al1 = __expf(m1 - mn1);
        m0 = mn0;
        m1 = mn1;
#pragma unroll
        for (int nt = 0; nt < 8; nt++) {
            co[nt][0] *= al0; co[nt][1] *= al0;
            co[nt][2] *= al1; co[nt][3] *= al1;
        }

        const uint32_t* VhB = smw + VHOFF + st * 64 * VSTW;
        const uint32_t* VlB = smw + VLOFF + st * 64 * VSTW;
        float s0 = 0.0f, s1 = 0.0f;

        // ---- fused exp + PV: P fragments (fp16) in registers, V hi/lo LDS.64
#pragma unroll
        for (int ks2 = 0; ks2 < 4; ks2++) {
            const int t0 = 2 * ks2, t1 = t0 + 1;
            float p00 = __expf(cs[t0][0] - mn0);
            float p01 = __expf(cs[t0][1] - mn0);
            float p02 = __expf(cs[t0][2] - mn1);
            float p03 = __expf(cs[t0][3] - mn1);
            float p10 = __expf(cs[t1][0] - mn0);
            float p11 = __expf(cs[t1][1] - mn0);
            float p12 = __expf(cs[t1][2] - mn1);
            float p13 = __expf(cs[t1][3] - mn1);
            s0 += (p00 + p01) + (p10 + p11);
            s1 += (p02 + p03) + (p12 + p13);

            uint32_t aP[4];
            aP[0] = pack_f16(p00, p01);
            aP[1] = pack_f16(p02, p03);
            aP[2] = pack_f16(p10, p11);
            aP[3] = pack_f16(p12, p13);

            const int w0 = ks2 * 8 + 2 * qd;   // interleaved: words (qd, qd+4) adjacent
#pragma unroll
            for (int nt = 0; nt < 8; nt++) {
                uint2 vb = *(const uint2*)(VhB + (nt * 8 + grp) * VSTW + w0);
                uint32_t b[2];
                b[0] = vb.x; b[1] = vb.y;
                mma16h(co[nt], aP, b);
                uint2 vl2 = *(const uint2*)(VlB + (nt * 8 + grp) * VSTW + w0);
                b[0] = vl2.x; b[1] = vl2.y;
                mma16h(co[nt], aP, b);
            }
        }

        s0 += __shfl_xor_sync(0xffffffffu, s0, 1);
        s0 += __shfl_xor_sync(0xffffffffu, s0, 2);
        s1 += __shfl_xor_sync(0xffffffffu, s1, 1);
        s1 += __shfl_xor_sync(0xffffffffu, s1, 2);
        l0 = l0 * al0 + s0;
        l1 = l1 * al1 + s1;
    }

    const int b_ = bh >> 4;
    const int h  = bh & 15;
    const float inv0 = 1.0f / l0, inv1 = 1.0f / l1;
    const int q0 = qt * 128 + r0 + grp;
#pragma unroll
    for (int nt = 0; nt < 8; nt++) {
        int n = nt * 8 + 2 * qd;
        *(float2*)&go[((size_t)(b_ * SS + q0) * HH + h) * HDD + n] =
            make_float2(co[nt][0] * inv0, co[nt][1] * inv0);
        *(float2*)&go[((size_t)(b_ * SS + q0 + 8) * HH + h) * HDD + n] =
            make_float2(co[nt][2] * inv1, co[nt][3] * inv1);
    }
}

// ---------------------------------------------------------------------------
extern "C" void kernel_launch(void* const* d_in, const int* in_sizes, int n_in,
                              void* d_out, int out_size)
{
    const float* x  = (const float*)d_in[0];
    const float* wq = (const float*)d_in[1];
    const float* bq = (const float*)d_in[2];
    const float* wk = (const float*)d_in[3];
    const float* bk = (const float*)d_in[4];
    const float* wv = (const float*)d_in[5];
    const float* bv = (const float*)d_in[6];
    const float* wo = (const float*)d_in[7];
    const float* bo = (const float*)d_in[8];
    float* out = (float*)d_out;

    float *gq, *gk, *go;
    __half *gvh, *gvl;
    __nv_bfloat16 *xhi, *xlo, *ohi, *olo, *wthi, *wtlo;
    cudaGetSymbolAddress((void**)&gq,   g_q);
    cudaGetSymbolAddress((void**)&gk,   g_k);
    cudaGetSymbolAddress((void**)&gvh,  g_vhi);
    cudaGetSymbolAddress((void**)&gvl,  g_vlo);
    cudaGetSymbolAddress((void**)&go,   g_o);
    cudaGetSymbolAddress((void**)&xhi,  g_xhi);
    cudaGetSymbolAddress((void**)&xlo,  g_xlo);
    cudaGetSymbolAddress((void**)&ohi,  g_ohi);
    cudaGetSymbolAddress((void**)&olo,  g_olo);
    cudaGetSymbolAddress((void**)&wthi, g_wthi);
    cudaGetSymbolAddress((void**)&wtlo, g_wtlo);

    cudaFuncSetAttribute(gemm_qkv, cudaFuncAttributeMaxDynamicSharedMemorySize, GEMM_SMEM);
    cudaFuncSetAttribute(gemm_o,   cudaFuncAttributeMaxDynamicSharedMemorySize, GEMM_SMEM);
    cudaFuncSetAttribute(flash_kernel, cudaFuncAttributeMaxDynamicSharedMemorySize, FLASH_SMEM);

    // prep
    split_kernel<<<(MROWS * DD / 4 + 255) / 256, 256>>>(x, xhi, xlo, MROWS * DD / 4);
    transpose_split_kernel<<<dim3(NCOLS / 32, DD / 32, 4), 256>>>(wq, wk, wv, wo, wthi, wtlo);

    gemm_qkv<<<dim3(NCOLS / 64, MROWS / 128, 3), 256, GEMM_SMEM>>>(
        xhi, xlo, wthi, wtlo, bq, bk, bv, gq, gk, gvh, gvl);

    flash_kernel<<<dim3(SS / 128, BB * HH), 256, FLASH_SMEM>>>(gq, gk, gvh, gvl, go);

    split_kernel<<<(MROWS * NCOLS / 4 + 255) / 256, 256>>>(go, ohi, olo, MROWS * NCOLS / 4);
    gemm_o<<<dim3(NCOLS / 64, MROWS / 128), 256, GEMM_SMEM>>>(
        ohi, olo, wthi + 3 * WSZ, wtlo + 3 * WSZ, bo, out);
}